// round 1
// baseline (speedup 1.0000x reference)
#include <cuda_runtime.h>

#define Dd     1024
#define Hh     16
#define HDim   64
#define NBatch 2
#define Seq    2048

// Scratch (statics are the sanctioned way to get scratch)
__device__ float g_Q[NBatch * Hh * Seq * HDim];     // [N,H,S,hd]
__device__ float g_K[NBatch * Hh * Seq * HDim];
__device__ float g_V[NBatch * Hh * Seq * HDim];
__device__ float g_Ctx[NBatch * Seq * Dd];          // [N,S,D] attention context

// ---------------------------------------------------------------------------
// SGEMM core: C[128x128] tile of A[M,1024] * W[1024,1024]^T
// A row-major [M,K], W row-major [N,K] (torch Linear weight), so both tiles
// are K-contiguous loads. 256 threads, 8x8 per-thread register tile.
// ---------------------------------------------------------------------------
__device__ __forceinline__ void sgemm_tile(
    const float* __restrict__ A, const float* __restrict__ W,
    float (&As)[16][128], float (&Bs)[16][128],
    float (&acc)[8][8], int m0, int n0)
{
    const int tid = threadIdx.x;
    const int lr  = tid >> 2;          // 0..63  (row within tile)
    const int lc  = (tid & 3) << 2;    // 0,4,8,12 (k offset, float4)
    const int tr  = tid >> 4;          // 0..15
    const int tc  = tid & 15;          // 0..15

    const float* Ap = A + (m0 + lr) * Dd + lc;
    const float* Wp = W + (n0 + lr) * Dd + lc;

    for (int k0 = 0; k0 < Dd; k0 += 16) {
#pragma unroll
        for (int rr = 0; rr < 2; rr++) {
            float4 a = *(const float4*)(Ap + rr * 64 * Dd + k0);
            As[lc + 0][lr + rr * 64] = a.x;
            As[lc + 1][lr + rr * 64] = a.y;
            As[lc + 2][lr + rr * 64] = a.z;
            As[lc + 3][lr + rr * 64] = a.w;
            float4 b = *(const float4*)(Wp + rr * 64 * Dd + k0);
            Bs[lc + 0][lr + rr * 64] = b.x;
            Bs[lc + 1][lr + rr * 64] = b.y;
            Bs[lc + 2][lr + rr * 64] = b.z;
            Bs[lc + 3][lr + rr * 64] = b.w;
        }
        __syncthreads();
#pragma unroll
        for (int k = 0; k < 16; k++) {
            float ra[8], rb[8];
            *(float4*)(ra)     = *(const float4*)(&As[k][tr * 8]);
            *(float4*)(ra + 4) = *(const float4*)(&As[k][tr * 8 + 4]);
            *(float4*)(rb)     = *(const float4*)(&Bs[k][tc * 8]);
            *(float4*)(rb + 4) = *(const float4*)(&Bs[k][tc * 8 + 4]);
#pragma unroll
            for (int i = 0; i < 8; i++)
#pragma unroll
                for (int j = 0; j < 8; j++)
                    acc[i][j] += ra[i] * rb[j];
        }
        __syncthreads();
    }
}

// ---------------------------------------------------------------------------
// Fused QKV projection: z = 0/1/2 -> Q/K/V. Writes [N,H,S,hd] directly.
// ---------------------------------------------------------------------------
__global__ __launch_bounds__(256) void qkv_kernel(
    const float* __restrict__ X,
    const float* __restrict__ Wq, const float* __restrict__ bq,
    const float* __restrict__ Wk, const float* __restrict__ bk,
    const float* __restrict__ Wv, const float* __restrict__ bv)
{
    __shared__ float As[16][128];
    __shared__ float Bs[16][128];
    float acc[8][8];
#pragma unroll
    for (int i = 0; i < 8; i++)
#pragma unroll
        for (int j = 0; j < 8; j++) acc[i][j] = 0.f;

    const int z = blockIdx.z;
    const float* W    = (z == 0) ? Wq : (z == 1) ? Wk : Wv;
    const float* bias = (z == 0) ? bq : (z == 1) ? bk : bv;
    float* dst        = (z == 0) ? g_Q : (z == 1) ? g_K : g_V;

    const int m0 = blockIdx.y * 128;
    const int n0 = blockIdx.x * 128;

    sgemm_tile(X, W, As, Bs, acc, m0, n0);

    const int tr = threadIdx.x >> 4;
    const int tc = threadIdx.x & 15;
    float bv8[8];
#pragma unroll
    for (int j = 0; j < 8; j++) bv8[j] = bias[n0 + tc * 8 + j];

#pragma unroll
    for (int i = 0; i < 8; i++) {
        int m = m0 + tr * 8 + i;
        int b = m >> 11;           // batch (S = 2048)
        int s = m & 2047;
#pragma unroll
        for (int j = 0; j < 8; j += 4) {
            int n  = n0 + tc * 8 + j;
            int h  = n >> 6;
            int hd = n & 63;
            float4 v;
            v.x = acc[i][j + 0] + bv8[j + 0];
            v.y = acc[i][j + 1] + bv8[j + 1];
            v.z = acc[i][j + 2] + bv8[j + 2];
            v.w = acc[i][j + 3] + bv8[j + 3];
            *(float4*)&dst[(((b * Hh + h) * Seq + s) * HDim) + hd] = v;
        }
    }
}

// ---------------------------------------------------------------------------
// Output projection: d_out = g_Ctx @ Wo^T + bo, row-major [N*S, D]
// ---------------------------------------------------------------------------
__global__ __launch_bounds__(256) void oproj_kernel(
    const float* __restrict__ Wo, const float* __restrict__ bo,
    float* __restrict__ out)
{
    __shared__ float As[16][128];
    __shared__ float Bs[16][128];
    float acc[8][8];
#pragma unroll
    for (int i = 0; i < 8; i++)
#pragma unroll
        for (int j = 0; j < 8; j++) acc[i][j] = 0.f;

    const int m0 = blockIdx.y * 128;
    const int n0 = blockIdx.x * 128;

    sgemm_tile(g_Ctx, Wo, As, Bs, acc, m0, n0);

    const int tr = threadIdx.x >> 4;
    const int tc = threadIdx.x & 15;
    float bv8[8];
#pragma unroll
    for (int j = 0; j < 8; j++) bv8[j] = bo[n0 + tc * 8 + j];

#pragma unroll
    for (int i = 0; i < 8; i++) {
        int m = m0 + tr * 8 + i;
#pragma unroll
        for (int j = 0; j < 8; j += 4) {
            int n = n0 + tc * 8 + j;
            float4 v;
            v.x = acc[i][j + 0] + bv8[j + 0];
            v.y = acc[i][j + 1] + bv8[j + 1];
            v.z = acc[i][j + 2] + bv8[j + 2];
            v.w = acc[i][j + 3] + bv8[j + 3];
            *(float4*)&out[m * Dd + n] = v;
        }
    }
}

// ---------------------------------------------------------------------------
// Flash attention, causal. One block per (q-tile of 64, head, batch).
// 128 threads: trow 0..15 (4 query rows each), tcol 0..7 (8 score cols /
// 8 hd cols each). Smem = 48KB exactly: Qs + (K reused as P) + Vs.
// K tile XOR-swizzled on 16B units; P skew-stored: conflict-free LDS.
// ---------------------------------------------------------------------------
__global__ __launch_bounds__(128) void flash_kernel()
{
    __shared__ float Qs[64][64];
    __shared__ float KPs[64][64];   // K (swizzled) then reused for P (skewed)
    __shared__ float Vs[64][64];

    const int tid  = threadIdx.x;
    const int trow = tid >> 3;      // 0..15
    const int tcol = tid & 7;       // 0..7
    const int qt = blockIdx.x;
    const int h  = blockIdx.y;
    const int n  = blockIdx.z;

    const int headoff = (n * Hh + h) * Seq * HDim;
    const float* Qg = g_Q + headoff + qt * 64 * HDim;
    const float* Kg = g_K + headoff;
    const float* Vg = g_V + headoff;

    const int lrow = tid >> 1;           // 0..63
    const int lf   = (tid & 1) * 8;      // 0 or 8 (float4 index base)

    // Load Q tile, pre-scaled by 1/sqrt(hd) = 0.125
#pragma unroll
    for (int f = 0; f < 8; f++) {
        float4 v = *(const float4*)(Qg + lrow * HDim + (lf + f) * 4);
        v.x *= 0.125f; v.y *= 0.125f; v.z *= 0.125f; v.w *= 0.125f;
        *(float4*)&Qs[lrow][(lf + f) * 4] = v;
    }

    float m_i[4], l_i[4], o[4][8];
#pragma unroll
    for (int i = 0; i < 4; i++) {
        m_i[i] = -1e30f; l_i[i] = 0.f;
#pragma unroll
        for (int j = 0; j < 8; j++) o[i][j] = 0.f;
    }
    const int r0 = trow * 4;

    for (int kt = 0; kt <= qt; kt++) {
        __syncthreads();   // prior iteration done reading KPs/Vs
        const float* kg = Kg + kt * 64 * HDim;
        const float* vg = Vg + kt * 64 * HDim;
#pragma unroll
        for (int f = 0; f < 8; f++) {
            int fi = lf + f;
            float4 kv = *(const float4*)(kg + lrow * HDim + fi * 4);
            *(float4*)&KPs[lrow][(fi ^ (lrow & 7)) * 4] = kv;   // swizzle
            float4 vv = *(const float4*)(vg + lrow * HDim + fi * 4);
            *(float4*)&Vs[lrow][fi * 4] = vv;
        }
        __syncthreads();

        // S = Q K^T (Q pre-scaled)
        float s[4][8];
#pragma unroll
        for (int i = 0; i < 4; i++)
#pragma unroll
            for (int j = 0; j < 8; j++) s[i][j] = 0.f;

#pragma unroll
        for (int f = 0; f < 16; f++) {
            float4 q[4];
#pragma unroll
            for (int i = 0; i < 4; i++) q[i] = *(const float4*)&Qs[r0 + i][f * 4];
#pragma unroll
            for (int j = 0; j < 8; j++) {
                int c = tcol + 8 * j;
                float4 kk = *(const float4*)&KPs[c][(f ^ (c & 7)) * 4];
#pragma unroll
                for (int i = 0; i < 4; i++)
                    s[i][j] += q[i].x * kk.x + q[i].y * kk.y
                             + q[i].z * kk.z + q[i].w * kk.w;
            }
        }

        // Causal mask (diagonal tile only)
        if (kt == qt) {
#pragma unroll
            for (int i = 0; i < 4; i++)
#pragma unroll
                for (int j = 0; j < 8; j++)
                    if (tcol + 8 * j > r0 + i) s[i][j] = -1e30f;
        }

        // Online softmax update
        float mt[4];
#pragma unroll
        for (int i = 0; i < 4; i++) {
            mt[i] = s[i][0];
#pragma unroll
            for (int j = 1; j < 8; j++) mt[i] = fmaxf(mt[i], s[i][j]);
        }
#pragma unroll
        for (int d = 1; d < 8; d <<= 1)
#pragma unroll
            for (int i = 0; i < 4; i++)
                mt[i] = fmaxf(mt[i], __shfl_xor_sync(0xffffffffu, mt[i], d));

        float alpha[4];
#pragma unroll
        for (int i = 0; i < 4; i++) {
            float mn = fmaxf(m_i[i], mt[i]);
            alpha[i] = __expf(m_i[i] - mn);
            m_i[i]   = mn;
        }
        float rs[4] = {0.f, 0.f, 0.f, 0.f};
#pragma unroll
        for (int i = 0; i < 4; i++)
#pragma unroll
            for (int j = 0; j < 8; j++) {
                float p = __expf(s[i][j] - m_i[i]);
                s[i][j] = p;
                rs[i] += p;
            }
#pragma unroll
        for (int d = 1; d < 8; d <<= 1)
#pragma unroll
            for (int i = 0; i < 4; i++)
                rs[i] += __shfl_xor_sync(0xffffffffu, rs[i], d);
#pragma unroll
        for (int i = 0; i < 4; i++) {
            l_i[i] = l_i[i] * alpha[i] + rs[i];
#pragma unroll
            for (int j = 0; j < 8; j++) o[i][j] *= alpha[i];
        }

        __syncthreads();   // done reading KPs as K
        // Store P skewed: col' = (c + r) & 63  -> conflict-free read/write
#pragma unroll
        for (int i = 0; i < 4; i++)
#pragma unroll
            for (int j = 0; j < 8; j++)
                KPs[r0 + i][(tcol + 8 * j + r0 + i) & 63] = s[i][j];
        __syncthreads();

        // O += P V
#pragma unroll 4
        for (int c = 0; c < 64; c++) {
            float4 v0 = *(const float4*)&Vs[c][tcol * 4];
            float4 v1 = *(const float4*)&Vs[c][32 + tcol * 4];
#pragma unroll
            for (int i = 0; i < 4; i++) {
                float p = KPs[r0 + i][(c + r0 + i) & 63];
                o[i][0] += p * v0.x; o[i][1] += p * v0.y;
                o[i][2] += p * v0.z; o[i][3] += p * v0.w;
                o[i][4] += p * v1.x; o[i][5] += p * v1.y;
                o[i][6] += p * v1.z; o[i][7] += p * v1.w;
            }
        }
    }

    // Normalize and write context in [N,S,D] layout
#pragma unroll
    for (int i = 0; i < 4; i++) {
        float inv = 1.0f / l_i[i];
        int srow = qt * 64 + r0 + i;
        float* dst = g_Ctx + (n * Seq + srow) * Dd + h * HDim;
        float4 w0, w1;
        w0.x = o[i][0] * inv; w0.y = o[i][1] * inv;
        w0.z = o[i][2] * inv; w0.w = o[i][3] * inv;
        w1.x = o[i][4] * inv; w1.y = o[i][5] * inv;
        w1.z = o[i][6] * inv; w1.w = o[i][7] * inv;
        *(float4*)&dst[tcol * 4]      = w0;
        *(float4*)&dst[32 + tcol * 4] = w1;
    }
}

// ---------------------------------------------------------------------------
extern "C" void kernel_launch(void* const* d_in, const int* in_sizes, int n_in,
                              void* d_out, int out_size)
{
    (void)in_sizes; (void)n_in; (void)out_size;
    const float* X  = (const float*)d_in[0];
    const float* Wq = (const float*)d_in[1];
    const float* bq = (const float*)d_in[2];
    const float* Wk = (const float*)d_in[3];
    const float* bk = (const float*)d_in[4];
    const float* Wv = (const float*)d_in[5];
    const float* bv = (const float*)d_in[6];
    const float* Wo = (const float*)d_in[7];
    const float* bo = (const float*)d_in[8];

    dim3 gqkv(Dd / 128, (NBatch * Seq) / 128, 3);
    qkv_kernel<<<gqkv, 256>>>(X, Wq, bq, Wk, bk, Wv, bv);

    flash_kernel<<<dim3(Seq / 64, Hh, NBatch), 128>>>();

    dim3 go(Dd / 128, (NBatch * Seq) / 128);
    oproj_kernel<<<go, 256>>>(Wo, bo, (float*)d_out);
}

// round 3
// speedup vs baseline: 3.5085x; 3.5085x over previous
#include <cuda_runtime.h>
#include <cstdint>

#define Dd     1024
#define Hh     16
#define HDim   64
#define NBatch 2
#define Seq    2048

// Scratch (tf32-rounded f32 values)
__device__ float g_Q[NBatch * Hh * Seq * HDim];     // [N,H,S,hd], pre-scaled 0.125
__device__ float g_K[NBatch * Hh * Seq * HDim];
__device__ float g_V[NBatch * Hh * Seq * HDim];
__device__ float g_Ctx[NBatch * Seq * Dd];          // [N,S,D]

// ===========================================================================
// PTX helpers (plain sm_100-target features only: mma.sync / ldmatrix / cp.async)
// ===========================================================================
__device__ __forceinline__ uint32_t cvta_smem(const void* p) {
    uint32_t a;
    asm("{ .reg .u64 t; cvta.to.shared.u64 t, %1; cvt.u32.u64 %0, t; }"
        : "=r"(a) : "l"(p));
    return a;
}
__device__ __forceinline__ float f2tf(float f) {
    uint32_t u;
    asm("cvt.rna.tf32.f32 %0, %1;" : "=r"(u) : "f"(f));
    return __uint_as_float(u);
}
__device__ __forceinline__ void ldsm4(uint32_t addr, uint32_t* d) {
    asm volatile("ldmatrix.sync.aligned.m8n8.x4.shared.b16 {%0,%1,%2,%3}, [%4];"
                 : "=r"(d[0]), "=r"(d[1]), "=r"(d[2]), "=r"(d[3]) : "r"(addr));
}
__device__ __forceinline__ void mma8(float* c, const uint32_t* a, const uint32_t* b) {
    asm volatile(
        "mma.sync.aligned.m16n8k8.row.col.f32.tf32.tf32.f32 "
        "{%0,%1,%2,%3}, {%4,%5,%6,%7}, {%8,%9}, {%0,%1,%2,%3};"
        : "+f"(c[0]), "+f"(c[1]), "+f"(c[2]), "+f"(c[3])
        : "r"(a[0]), "r"(a[1]), "r"(a[2]), "r"(a[3]), "r"(b[0]), "r"(b[1]));
}
__device__ __forceinline__ void cp16(uint32_t dst, const void* src) {
    asm volatile("cp.async.ca.shared.global [%0], [%1], 16;" :: "r"(dst), "l"(src));
}
__device__ __forceinline__ void cp4(uint32_t dst, const void* src) {
    asm volatile("cp.async.ca.shared.global [%0], [%1], 4;" :: "r"(dst), "l"(src));
}
#define CP_COMMIT() asm volatile("cp.async.commit_group;" ::: "memory")
#define CP_WAIT0()  asm volatile("cp.async.wait_group 0;" ::: "memory")
__device__ __forceinline__ void sts_v4(uint32_t addr, float x, float y, float z, float w) {
    asm volatile("st.shared.v4.f32 [%0], {%1,%2,%3,%4};"
                 :: "r"(addr), "f"(x), "f"(y), "f"(z), "f"(w) : "memory");
}
__device__ __forceinline__ void sts_v2(uint32_t addr, float x, float y) {
    asm volatile("st.shared.v2.f32 [%0], {%1,%2};"
                 :: "r"(addr), "f"(x), "f"(y) : "memory");
}

// ===========================================================================
// tf32 mma.sync GEMM: C[128,128] tile of A[M,1024] @ W[1024,1024]^T
// A,W row-major K-major. 256 threads = 8 warps, warp tile 64x32.
// smem per stage: A 128x(32f)=16KB + B 16KB; 2 stages = 64KB dynamic.
// 16B-unit swizzle: unit' = unit ^ (row&7)  (rows are 128B).
// ===========================================================================
#define GSTAGE 32768

__device__ __forceinline__ void tc_gemm128(
    const float* __restrict__ A, const float* __restrict__ W,
    int m0, int n0, char* smem, float c[4][4][4])
{
    const int tid = threadIdx.x;
    const int wid = tid >> 5, lane = tid & 31;
    const int wm = wid & 1, wn = wid >> 1;
    const uint32_t sb = cvta_smem(smem);

    const int r0g = tid >> 3;       // 0..31
    const int u   = tid & 7;        // 16B unit within 128B row
    const float* Ap = A + (size_t)(m0 + r0g) * Dd + u * 4;
    const float* Wp = W + (size_t)(n0 + r0g) * Dd + u * 4;

#pragma unroll
    for (int mt = 0; mt < 4; mt++)
#pragma unroll
        for (int nt = 0; nt < 4; nt++)
#pragma unroll
            for (int k = 0; k < 4; k++) c[mt][nt][k] = 0.f;

    float4 ra[4], rb[4];
    // prologue: chunk 0
#pragma unroll
    for (int i = 0; i < 4; i++) {
        ra[i] = *(const float4*)(Ap + (size_t)(i * 32) * Dd);
        rb[i] = *(const float4*)(Wp + (size_t)(i * 32) * Dd);
    }
#pragma unroll
    for (int i = 0; i < 4; i++) {
        int row = r0g + i * 32;
        uint32_t sw = (uint32_t)(u ^ (row & 7)) << 4;
        sts_v4(sb + row * 128 + sw, f2tf(ra[i].x), f2tf(ra[i].y), f2tf(ra[i].z), f2tf(ra[i].w));
        sts_v4(sb + 16384 + row * 128 + sw, f2tf(rb[i].x), f2tf(rb[i].y), f2tf(rb[i].z), f2tf(rb[i].w));
    }
    __syncthreads();

    for (int k = 0; k < 32; k++) {
        const uint32_t cur = sb + (uint32_t)(k & 1) * GSTAGE;
        if (k < 31) {
            const int k0 = (k + 1) * 32;
#pragma unroll
            for (int i = 0; i < 4; i++) {
                ra[i] = *(const float4*)(Ap + (size_t)(i * 32) * Dd + k0);
                rb[i] = *(const float4*)(Wp + (size_t)(i * 32) * Dd + k0);
            }
        }
        const uint32_t Ab = cur, Bb = cur + 16384;
#pragma unroll
        for (int sp = 0; sp < 2; sp++) {
            uint32_t bq[4][4];
#pragma unroll
            for (int nt = 0; nt < 4; nt++) {
                int row = wn * 32 + nt * 8 + (lane & 7);
                uint32_t uu = (uint32_t)(sp * 4 + (lane >> 3));
                ldsm4(Bb + row * 128 + ((uu ^ (uint32_t)(row & 7)) << 4), bq[nt]);
            }
#pragma unroll
            for (int sh = 0; sh < 2; sh++) {
                const int s = sp * 2 + sh;
                uint32_t aq[4][4];
#pragma unroll
                for (int mt = 0; mt < 4; mt++) {
                    int row = wm * 64 + mt * 16 + (lane & 7) + ((lane >> 3) & 1) * 8;
                    uint32_t uu = (uint32_t)(2 * s + (lane >> 4));
                    ldsm4(Ab + row * 128 + ((uu ^ (uint32_t)(row & 7)) << 4), aq[mt]);
                }
#pragma unroll
                for (int mt = 0; mt < 4; mt++)
#pragma unroll
                    for (int nt = 0; nt < 4; nt++)
                        mma8(c[mt][nt], aq[mt], &bq[nt][sh * 2]);
            }
        }
        if (k < 31) {
            const uint32_t nxt = sb + (uint32_t)((k + 1) & 1) * GSTAGE;
#pragma unroll
            for (int i = 0; i < 4; i++) {
                int row = r0g + i * 32;
                uint32_t sw = (uint32_t)(u ^ (row & 7)) << 4;
                sts_v4(nxt + row * 128 + sw, f2tf(ra[i].x), f2tf(ra[i].y), f2tf(ra[i].z), f2tf(ra[i].w));
                sts_v4(nxt + 16384 + row * 128 + sw, f2tf(rb[i].x), f2tf(rb[i].y), f2tf(rb[i].z), f2tf(rb[i].w));
            }
        }
        __syncthreads();
    }
}

// ===========================================================================
// QKV projection: z = 0/1/2 -> Q/K/V, writes [N,H,S,hd], tf32-rounded.
// Q additionally pre-scaled by 1/sqrt(hd) = 0.125.
// ===========================================================================
__global__ __launch_bounds__(256, 1)
void qkv_tc_kernel(const float* __restrict__ X,
                   const float* __restrict__ Wq, const float* __restrict__ bq,
                   const float* __restrict__ Wk, const float* __restrict__ bk,
                   const float* __restrict__ Wv, const float* __restrict__ bv)
{
    extern __shared__ char sm[];
    const int z = blockIdx.z;
    const float* W    = (z == 0) ? Wq : (z == 1) ? Wk : Wv;
    const float* bias = (z == 0) ? bq : (z == 1) ? bk : bv;
    float* dst        = (z == 0) ? g_Q : (z == 1) ? g_K : g_V;
    const float scl   = (z == 0) ? 0.125f : 1.0f;

    const int m0 = blockIdx.y * 128;
    const int n0 = blockIdx.x * 128;

    float c[4][4][4];
    tc_gemm128(X, W, m0, n0, sm, c);

    const int tid = threadIdx.x;
    const int wid = tid >> 5, lane = tid & 31;
    const int wm = wid & 1, wn = wid >> 1;

#pragma unroll
    for (int mt = 0; mt < 4; mt++) {
#pragma unroll
        for (int h2 = 0; h2 < 2; h2++) {
            const int m = m0 + wm * 64 + mt * 16 + (lane >> 2) + h2 * 8;
            const int b = m >> 11;
            const int s = m & (Seq - 1);
#pragma unroll
            for (int nt = 0; nt < 4; nt++) {
                const int col = n0 + wn * 32 + nt * 8 + 2 * (lane & 3);
                const int hh = col >> 6, hd = col & 63;
                float2 v;
                v.x = f2tf((c[mt][nt][h2 * 2 + 0] + bias[col]) * scl);
                v.y = f2tf((c[mt][nt][h2 * 2 + 1] + bias[col + 1]) * scl);
                *(float2*)&dst[((size_t)(b * Hh + hh) * Seq + s) * HDim + hd] = v;
            }
        }
    }
}

// ===========================================================================
// Output projection: d_out = g_Ctx @ Wo^T + bo
// ===========================================================================
__global__ __launch_bounds__(256, 1)
void oproj_tc_kernel(const float* __restrict__ Wo, const float* __restrict__ bo,
                     float* __restrict__ out)
{
    extern __shared__ char sm[];
    const int m0 = blockIdx.y * 128;
    const int n0 = blockIdx.x * 128;

    float c[4][4][4];
    tc_gemm128(g_Ctx, Wo, m0, n0, sm, c);

    const int tid = threadIdx.x;
    const int wid = tid >> 5, lane = tid & 31;
    const int wm = wid & 1, wn = wid >> 1;

#pragma unroll
    for (int mt = 0; mt < 4; mt++) {
#pragma unroll
        for (int h2 = 0; h2 < 2; h2++) {
            const int m = m0 + wm * 64 + mt * 16 + (lane >> 2) + h2 * 8;
#pragma unroll
            for (int nt = 0; nt < 4; nt++) {
                const int col = n0 + wn * 32 + nt * 8 + 2 * (lane & 3);
                float2 v;
                v.x = c[mt][nt][h2 * 2 + 0] + bo[col];
                v.y = c[mt][nt][h2 * 2 + 1] + bo[col + 1];
                *(float2*)&out[(size_t)m * Dd + col] = v;
            }
        }
    }
}

// ===========================================================================
// Flash attention with tf32 mma.sync. Block = 128 q-rows x (head, batch).
// 8 warps x 16 q-rows. kt tiles of 64. K/V cp.async double-buffered.
// V transposed into smem (Vt[hd][t]) so PV B-operand is K-major (plain ldmatrix).
// P is warp-private in Ps (rows = own warp's 16 q-rows).
// smem: Ks0,Vt0,Ks1,Vt1 (4x16KB) + Ps (128x256B = 32KB) = 96KB.
// ===========================================================================
#define QT 128

__global__ __launch_bounds__(256, 1) void flash_tc_kernel()
{
    extern __shared__ char sm[];
    const uint32_t sb = cvta_smem(sm);
    const uint32_t KsB[2] = { sb, sb + 32768 };
    const uint32_t VtB[2] = { sb + 16384, sb + 49152 };
    const uint32_t Ps = sb + 65536;

    const int tid = threadIdx.x, wid = tid >> 5, lane = tid & 31;
    const int qt = blockIdx.x, h = blockIdx.y, n = blockIdx.z;
    const size_t hoff = (size_t)(n * Hh + h) * Seq * HDim;
    const float* Qg = g_Q + hoff + (size_t)qt * QT * HDim;
    const float* Kg = g_K + hoff;
    const float* Vg = g_V + hoff;

    // ---- Stage Q (128x64) into Ps (rows 256B, 16 units, swizzled), load frags
#pragma unroll
    for (int i = 0; i < 8; i++) {
        int flat = i * 256 + tid;           // 2048 16B-units
        int r = flat >> 4, uu = flat & 15;
        float4 v = *(const float4*)(Qg + r * 64 + uu * 4);
        sts_v4(Ps + r * 256 + (((uint32_t)(uu ^ (r & 7))) << 4), v.x, v.y, v.z, v.w);
    }
    __syncthreads();
    const int Rm = wid * 16;
    uint32_t qf[8][4];
#pragma unroll
    for (int s = 0; s < 8; s++) {
        int row = Rm + (lane & 7) + ((lane >> 3) & 1) * 8;
        uint32_t uu = (uint32_t)(2 * s + (lane >> 4));
        ldsm4(Ps + row * 256 + ((uu ^ (uint32_t)(row & 7)) << 4), qf[s]);
    }
    __syncthreads();

    float o[8][4];
#pragma unroll
    for (int nt = 0; nt < 8; nt++)
#pragma unroll
        for (int k = 0; k < 4; k++) o[nt][k] = 0.f;
    float m1 = -1e30f, m2 = -1e30f, l1 = 0.f, l2 = 0.f;

    const int nkt = 2 * qt + 2;

    // issue loads for kt=0 into buffer 0
    {
        const float* kg = Kg; const float* vg = Vg;
#pragma unroll
        for (int i = 0; i < 4; i++) {                 // K: 1024 units
            int flat = i * 256 + tid;
            int t = flat >> 4, uu = flat & 15;
            cp16(KsB[0] + t * 256 + (((uint32_t)(uu ^ (t & 7))) << 4), kg + t * 64 + uu * 4);
        }
#pragma unroll
        for (int i = 0; i < 16; i++) {                // V transpose: 4096 scalars
            int flat = i * 256 + tid;
            int hd = flat & 63, t = flat >> 6;
            cp4(VtB[0] + hd * 256 + (((uint32_t)((t >> 2) ^ (hd & 7))) << 4) + (t & 3) * 4,
                vg + t * 64 + hd);
        }
        CP_COMMIT();
    }

    for (int j = 0; j < nkt; j++) {
        CP_WAIT0();
        __syncthreads();                 // cur buffer visible to all; prev compute done
        const int b = j & 1;
        if (j + 1 < nkt) {
            const float* kg = Kg + (size_t)(j + 1) * 64 * HDim;
            const float* vg = Vg + (size_t)(j + 1) * 64 * HDim;
            const int nb = b ^ 1;
#pragma unroll
            for (int i = 0; i < 4; i++) {
                int flat = i * 256 + tid;
                int t = flat >> 4, uu = flat & 15;
                cp16(KsB[nb] + t * 256 + (((uint32_t)(uu ^ (t & 7))) << 4), kg + t * 64 + uu * 4);
            }
#pragma unroll
            for (int i = 0; i < 16; i++) {
                int flat = i * 256 + tid;
                int hd = flat & 63, t = flat >> 6;
                cp4(VtB[nb] + hd * 256 + (((uint32_t)((t >> 2) ^ (hd & 7))) << 4) + (t & 3) * 4,
                    vg + t * 64 + hd);
            }
            CP_COMMIT();
        }

        // ---- S = Q K^T  (Q pre-scaled by 0.125 at qkv epilogue)
        float sfr[8][4];
#pragma unroll
        for (int nt = 0; nt < 8; nt++)
#pragma unroll
            for (int k = 0; k < 4; k++) sfr[nt][k] = 0.f;
#pragma unroll
        for (int sp = 0; sp < 4; sp++) {
#pragma unroll
            for (int nt = 0; nt < 8; nt++) {
                uint32_t bq[4];
                int row = nt * 8 + (lane & 7);
                uint32_t uu = (uint32_t)(sp * 4 + (lane >> 3));
                ldsm4(KsB[b] + row * 256 + ((uu ^ (uint32_t)(row & 7)) << 4), bq);
                mma8(sfr[nt], qf[2 * sp], &bq[0]);
                mma8(sfr[nt], qf[2 * sp + 1], &bq[2]);
            }
        }

        // ---- causal mask (only needed on the last two kt tiles)
        const int r1 = qt * QT + Rm + (lane >> 2);
        if (j >= 2 * qt) {
            const int cb = j * 64 + 2 * (lane & 3);
#pragma unroll
            for (int nt = 0; nt < 8; nt++) {
                const int c0 = cb + nt * 8;
                if (c0     > r1)     sfr[nt][0] = -1e30f;
                if (c0 + 1 > r1)     sfr[nt][1] = -1e30f;
                if (c0     > r1 + 8) sfr[nt][2] = -1e30f;
                if (c0 + 1 > r1 + 8) sfr[nt][3] = -1e30f;
            }
        }

        // ---- online softmax (rows r1, r1+8; quad lanes share rows)
        float mt1 = -1e30f, mt2 = -1e30f;
#pragma unroll
        for (int nt = 0; nt < 8; nt++) {
            mt1 = fmaxf(mt1, fmaxf(sfr[nt][0], sfr[nt][1]));
            mt2 = fmaxf(mt2, fmaxf(sfr[nt][2], sfr[nt][3]));
        }
        mt1 = fmaxf(mt1, __shfl_xor_sync(0xffffffffu, mt1, 1));
        mt1 = fmaxf(mt1, __shfl_xor_sync(0xffffffffu, mt1, 2));
        mt2 = fmaxf(mt2, __shfl_xor_sync(0xffffffffu, mt2, 1));
        mt2 = fmaxf(mt2, __shfl_xor_sync(0xffffffffu, mt2, 2));

        const float mn1 = fmaxf(m1, mt1), al1 = __expf(m1 - mn1);
        const float mn2 = fmaxf(m2, mt2), al2 = __expf(m2 - mn2);
        m1 = mn1; m2 = mn2;
        float rs1 = 0.f, rs2 = 0.f;
#pragma unroll
        for (int nt = 0; nt < 8; nt++) {
            sfr[nt][0] = __expf(sfr[nt][0] - m1); rs1 += sfr[nt][0];
            sfr[nt][1] = __expf(sfr[nt][1] - m1); rs1 += sfr[nt][1];
            sfr[nt][2] = __expf(sfr[nt][2] - m2); rs2 += sfr[nt][2];
            sfr[nt][3] = __expf(sfr[nt][3] - m2); rs2 += sfr[nt][3];
        }
        rs1 += __shfl_xor_sync(0xffffffffu, rs1, 1);
        rs1 += __shfl_xor_sync(0xffffffffu, rs1, 2);
        rs2 += __shfl_xor_sync(0xffffffffu, rs2, 1);
        rs2 += __shfl_xor_sync(0xffffffffu, rs2, 2);
        l1 = l1 * al1 + rs1;
        l2 = l2 * al2 + rs2;
#pragma unroll
        for (int nt = 0; nt < 8; nt++) {
            o[nt][0] *= al1; o[nt][1] *= al1;
            o[nt][2] *= al2; o[nt][3] *= al2;
        }

        // ---- store P (warp-private rows) tf32-rounded
        {
            const int rr1 = Rm + (lane >> 2);
            const int rr2 = rr1 + 8;
#pragma unroll
            for (int nt = 0; nt < 8; nt++) {
                const int c = nt * 8 + 2 * (lane & 3);
                uint32_t a1 = Ps + rr1 * 256 + (((uint32_t)((c >> 2) ^ (rr1 & 7))) << 4) + (c & 3) * 4;
                sts_v2(a1, f2tf(sfr[nt][0]), f2tf(sfr[nt][1]));
                uint32_t a2 = Ps + rr2 * 256 + (((uint32_t)((c >> 2) ^ (rr2 & 7))) << 4) + (c & 3) * 4;
                sts_v2(a2, f2tf(sfr[nt][2]), f2tf(sfr[nt][3]));
            }
        }
        __syncwarp();

        // ---- O += P V   (A = P from Ps, B = Vt, both K-major in t)
#pragma unroll
        for (int sp = 0; sp < 4; sp++) {
            uint32_t a0[4], a1[4];
            {
                int row = Rm + (lane & 7) + ((lane >> 3) & 1) * 8;
                uint32_t uu0 = (uint32_t)(2 * (2 * sp) + (lane >> 4));
                ldsm4(Ps + row * 256 + ((uu0 ^ (uint32_t)(row & 7)) << 4), a0);
                uint32_t uu1 = (uint32_t)(2 * (2 * sp + 1) + (lane >> 4));
                ldsm4(Ps + row * 256 + ((uu1 ^ (uint32_t)(row & 7)) << 4), a1);
            }
#pragma unroll
            for (int nt = 0; nt < 8; nt++) {
                uint32_t bq[4];
                int row = nt * 8 + (lane & 7);
                uint32_t uu = (uint32_t)(sp * 4 + (lane >> 3));
                ldsm4(VtB[b] + row * 256 + ((uu ^ (uint32_t)(row & 7)) << 4), bq);
                mma8(o[nt], a0, &bq[0]);
                mma8(o[nt], a1, &bq[2]);
            }
        }
        // next iteration's top __syncthreads() separates this compute from
        // buffer overwrite; Ps is warp-private so no extra sync needed.
    }

    // ---- epilogue: normalize, tf32-round, write g_Ctx [N,S,D]
    const float inv1 = 1.f / l1, inv2 = 1.f / l2;
    const int r1g = qt * QT + Rm + (lane >> 2);
    float* C1 = g_Ctx + ((size_t)n * Seq + r1g) * Dd + h * HDim;
    float* C2 = C1 + (size_t)8 * Dd;
#pragma unroll
    for (int nt = 0; nt < 8; nt++) {
        const int c = nt * 8 + 2 * (lane & 3);
        float2 v1, v2;
        v1.x = f2tf(o[nt][0] * inv1); v1.y = f2tf(o[nt][1] * inv1);
        v2.x = f2tf(o[nt][2] * inv2); v2.y = f2tf(o[nt][3] * inv2);
        *(float2*)&C1[c] = v1;
        *(float2*)&C2[c] = v2;
    }
}

// ===========================================================================
extern "C" void kernel_launch(void* const* d_in, const int* in_sizes, int n_in,
                              void* d_out, int out_size)
{
    (void)in_sizes; (void)n_in; (void)out_size;
    const float* X  = (const float*)d_in[0];
    const float* Wq = (const float*)d_in[1];
    const float* bq = (const float*)d_in[2];
    const float* Wk = (const float*)d_in[3];
    const float* bk = (const float*)d_in[4];
    const float* Wv = (const float*)d_in[5];
    const float* bv = (const float*)d_in[6];
    const float* Wo = (const float*)d_in[7];
    const float* bo = (const float*)d_in[8];

    const int gemm_smem  = 2 * GSTAGE;            // 64KB
    const int flash_smem = 4 * 16384 + 32768;     // 96KB
    cudaFuncSetAttribute(qkv_tc_kernel,
                         cudaFuncAttributeMaxDynamicSharedMemorySize, gemm_smem);
    cudaFuncSetAttribute(oproj_tc_kernel,
                         cudaFuncAttributeMaxDynamicSharedMemorySize, gemm_smem);
    cudaFuncSetAttribute(flash_tc_kernel,
                         cudaFuncAttributeMaxDynamicSharedMemorySize, flash_smem);

    dim3 gqkv(Dd / 128, (NBatch * Seq) / 128, 3);
    qkv_tc_kernel<<<gqkv, 256, gemm_smem>>>(X, Wq, bq, Wk, bk, Wv, bv);

    flash_tc_kernel<<<dim3(Seq / QT, Hh, NBatch), 256, flash_smem>>>();

    dim3 go(Dd / 128, (NBatch * Seq) / 128);
    oproj_tc_kernel<<<go, 256, gemm_smem>>>(Wo, bo, (float*)d_out);
}

// round 4
// speedup vs baseline: 4.0669x; 1.1592x over previous
#include <cuda_runtime.h>
#include <cstdint>

#define Dd     1024
#define Hh     16
#define HDim   64
#define NBatch 2
#define Seq    2048

// Scratch
__device__ float g_Q  [NBatch * Hh * Seq * HDim];   // [N,H,S,hd], tf32, pre-scaled 0.125
__device__ float g_K  [NBatch * Hh * Seq * HDim];   // [N,H,S,hd], tf32
__device__ float g_Vt [NBatch * Hh * HDim * Seq];   // [N,H,hd,S], tf32 (transposed!)
__device__ float g_Ctx[NBatch * Seq * Dd];          // [N,S,D], tf32
__device__ float g_Xr [NBatch * Seq * Dd];          // tf32-rounded X
__device__ float g_Wr [4 * Dd * Dd];                // tf32-rounded Wq,Wk,Wv,Wo

// ===========================================================================
// PTX helpers
// ===========================================================================
__device__ __forceinline__ uint32_t cvta_smem(const void* p) {
    uint32_t a;
    asm("{ .reg .u64 t; cvta.to.shared.u64 t, %1; cvt.u32.u64 %0, t; }"
        : "=r"(a) : "l"(p));
    return a;
}
__device__ __forceinline__ float f2tf(float f) {
    uint32_t u;
    asm("cvt.rna.tf32.f32 %0, %1;" : "=r"(u) : "f"(f));
    return __uint_as_float(u);
}
__device__ __forceinline__ void ldsm4(uint32_t addr, uint32_t* d) {
    asm volatile("ldmatrix.sync.aligned.m8n8.x4.shared.b16 {%0,%1,%2,%3}, [%4];"
                 : "=r"(d[0]), "=r"(d[1]), "=r"(d[2]), "=r"(d[3]) : "r"(addr));
}
__device__ __forceinline__ void mma8(float* c, const uint32_t* a, const uint32_t* b) {
    asm volatile(
        "mma.sync.aligned.m16n8k8.row.col.f32.tf32.tf32.f32 "
        "{%0,%1,%2,%3}, {%4,%5,%6,%7}, {%8,%9}, {%0,%1,%2,%3};"
        : "+f"(c[0]), "+f"(c[1]), "+f"(c[2]), "+f"(c[3])
        : "r"(a[0]), "r"(a[1]), "r"(a[2]), "r"(a[3]), "r"(b[0]), "r"(b[1]));
}
__device__ __forceinline__ void cp16(uint32_t dst, const void* src) {
    asm volatile("cp.async.ca.shared.global [%0], [%1], 16;" :: "r"(dst), "l"(src));
}
#define CP_COMMIT() asm volatile("cp.async.commit_group;" ::: "memory")
#define CP_WAIT0()  asm volatile("cp.async.wait_group 0;" ::: "memory")
#define CP_WAIT1()  asm volatile("cp.async.wait_group 1;" ::: "memory")
__device__ __forceinline__ void sts_v4(uint32_t addr, float x, float y, float z, float w) {
    asm volatile("st.shared.v4.f32 [%0], {%1,%2,%3,%4};"
                 :: "r"(addr), "f"(x), "f"(y), "f"(z), "f"(w) : "memory");
}
__device__ __forceinline__ void sts_v2(uint32_t addr, float x, float y) {
    asm volatile("st.shared.v2.f32 [%0], {%1,%2};"
                 :: "r"(addr), "f"(x), "f"(y) : "memory");
}

// ===========================================================================
// Pre-round: tf32-round X and the 4 weight matrices into scratch (once).
// ===========================================================================
__global__ __launch_bounds__(256) void round_kernel(
    const float* __restrict__ X,
    const float* __restrict__ Wq, const float* __restrict__ Wk,
    const float* __restrict__ Wv, const float* __restrict__ Wo)
{
    const uint32_t u = blockIdx.x * blockDim.x + threadIdx.x;   // float4 unit
    const float4* src;
    float4* dst;
    if (u < (1u << 20)) {                 // X: 2^20 float4
        src = (const float4*)X + u;
        dst = (float4*)g_Xr + u;
    } else {
        uint32_t w = u - (1u << 20);
        uint32_t sel = w >> 18;           // 2^18 float4 per W
        uint32_t off = w & ((1u << 18) - 1);
        const float* Ws = (sel == 0) ? Wq : (sel == 1) ? Wk : (sel == 2) ? Wv : Wo;
        src = (const float4*)Ws + off;
        dst = (float4*)g_Wr + w;
    }
    float4 v = *src;
    v.x = f2tf(v.x); v.y = f2tf(v.y); v.z = f2tf(v.z); v.w = f2tf(v.w);
    *dst = v;
}

// ===========================================================================
// tf32 mma.sync GEMM, cp.async 3-stage pipeline.
// C[128,128] tile of A[M,1024] @ W[1024,1024]^T, operands pre-rounded tf32.
// 256 threads = 8 warps, warp tile 64x32. Stage = A 16KB + B 16KB = 32KB.
// ===========================================================================
#define GSTAGE 32768
#define GNST   3

__device__ __forceinline__ void gemm_issue_stage(
    const float* __restrict__ A, const float* __restrict__ W,
    int m0, int n0, uint32_t sb, int s, int tid)
{
    const uint32_t buf = sb + (uint32_t)(s % GNST) * GSTAGE;
    const int k0 = s * 32;
#pragma unroll
    for (int i = 0; i < 4; i++) {
        const int flat = i * 256 + tid;
        const int r = flat >> 3, u = flat & 7;
        const uint32_t sw = (uint32_t)(u ^ (r & 7)) << 4;
        cp16(buf + r * 128 + sw,         A + (size_t)(m0 + r) * Dd + k0 + u * 4);
        cp16(buf + 16384 + r * 128 + sw, W + (size_t)(n0 + r) * Dd + k0 + u * 4);
    }
}

__device__ __forceinline__ void tc_gemm128(
    const float* __restrict__ A, const float* __restrict__ W,
    int m0, int n0, char* smem, float c[4][4][4])
{
    const int tid = threadIdx.x;
    const int wid = tid >> 5, lane = tid & 31;
    const int wm = wid & 1, wn = wid >> 1;
    const uint32_t sb = cvta_smem(smem);

#pragma unroll
    for (int mt = 0; mt < 4; mt++)
#pragma unroll
        for (int nt = 0; nt < 4; nt++)
#pragma unroll
            for (int k = 0; k < 4; k++) c[mt][nt][k] = 0.f;

    gemm_issue_stage(A, W, m0, n0, sb, 0, tid); CP_COMMIT();
    gemm_issue_stage(A, W, m0, n0, sb, 1, tid); CP_COMMIT();

    for (int k = 0; k < 32; k++) {
        CP_WAIT1();
        __syncthreads();
        if (k + 2 < 32) gemm_issue_stage(A, W, m0, n0, sb, k + 2, tid);
        CP_COMMIT();                      // always commit (empty group OK)

        const uint32_t cur = sb + (uint32_t)(k % GNST) * GSTAGE;
        const uint32_t Ab = cur, Bb = cur + 16384;
#pragma unroll
        for (int sp = 0; sp < 2; sp++) {
            uint32_t bq[4][4];
#pragma unroll
            for (int nt = 0; nt < 4; nt++) {
                int row = wn * 32 + nt * 8 + (lane & 7);
                uint32_t uu = (uint32_t)(sp * 4 + (lane >> 3));
                ldsm4(Bb + row * 128 + ((uu ^ (uint32_t)(row & 7)) << 4), bq[nt]);
            }
#pragma unroll
            for (int sh = 0; sh < 2; sh++) {
                const int s = sp * 2 + sh;
                uint32_t aq[4][4];
#pragma unroll
                for (int mt = 0; mt < 4; mt++) {
                    int row = wm * 64 + mt * 16 + (lane & 7) + ((lane >> 3) & 1) * 8;
                    uint32_t uu = (uint32_t)(2 * s + (lane >> 4));
                    ldsm4(Ab + row * 128 + ((uu ^ (uint32_t)(row & 7)) << 4), aq[mt]);
                }
#pragma unroll
                for (int mt = 0; mt < 4; mt++)
#pragma unroll
                    for (int nt = 0; nt < 4; nt++)
                        mma8(c[mt][nt], aq[mt], &bq[nt][sh * 2]);
            }
        }
    }
}

// ===========================================================================
// QKV projection: z = 0/1/2 -> Q/K/V.
// Q,K -> [N,H,S,hd] (Q scaled 0.125); V -> g_Vt [N,H,hd,S] (transposed).
// ===========================================================================
__global__ __launch_bounds__(256, 2)
void qkv_tc_kernel(const float* __restrict__ bq, const float* __restrict__ bk,
                   const float* __restrict__ bv)
{
    extern __shared__ char sm[];
    const int z = blockIdx.z;
    const float* W    = g_Wr + (size_t)z * Dd * Dd;
    const float* bias = (z == 0) ? bq : (z == 1) ? bk : bv;

    const int m0 = blockIdx.y * 128;
    const int n0 = blockIdx.x * 128;

    float c[4][4][4];
    tc_gemm128(g_Xr, W, m0, n0, sm, c);

    const int tid = threadIdx.x;
    const int wid = tid >> 5, lane = tid & 31;
    const int wm = wid & 1, wn = wid >> 1;
    const float scl = (z == 0) ? 0.125f : 1.0f;

    if (z < 2) {
        float* dst = (z == 0) ? g_Q : g_K;
#pragma unroll
        for (int mt = 0; mt < 4; mt++) {
#pragma unroll
            for (int h2 = 0; h2 < 2; h2++) {
                const int m = m0 + wm * 64 + mt * 16 + (lane >> 2) + h2 * 8;
                const int b = m >> 11;
                const int s = m & (Seq - 1);
#pragma unroll
                for (int nt = 0; nt < 4; nt++) {
                    const int col = n0 + wn * 32 + nt * 8 + 2 * (lane & 3);
                    const int hh = col >> 6, hd = col & 63;
                    float2 v;
                    v.x = f2tf((c[mt][nt][h2 * 2 + 0] + bias[col]) * scl);
                    v.y = f2tf((c[mt][nt][h2 * 2 + 1] + bias[col + 1]) * scl);
                    *(float2*)&dst[((size_t)(b * Hh + hh) * Seq + s) * HDim + hd] = v;
                }
            }
        }
    } else {
        // V: write transposed [N,H,hd,S]
#pragma unroll
        for (int mt = 0; mt < 4; mt++) {
#pragma unroll
            for (int h2 = 0; h2 < 2; h2++) {
                const int m = m0 + wm * 64 + mt * 16 + (lane >> 2) + h2 * 8;
                const int b = m >> 11;
                const int s = m & (Seq - 1);
#pragma unroll
                for (int nt = 0; nt < 4; nt++) {
                    const int col = n0 + wn * 32 + nt * 8 + 2 * (lane & 3);
                    const int hh = col >> 6, hd = col & 63;
                    float* dp = g_Vt + ((size_t)(b * Hh + hh) * HDim + hd) * Seq + s;
                    dp[0]   = f2tf(c[mt][nt][h2 * 2 + 0] + bias[col]);
                    dp[Seq] = f2tf(c[mt][nt][h2 * 2 + 1] + bias[col + 1]);
                }
            }
        }
    }
}

// ===========================================================================
// Output projection: d_out = g_Ctx @ Wo^T + bo (full fp32 output)
// ===========================================================================
__global__ __launch_bounds__(256, 2)
void oproj_tc_kernel(const float* __restrict__ bo, float* __restrict__ out)
{
    extern __shared__ char sm[];
    const int m0 = blockIdx.y * 128;
    const int n0 = blockIdx.x * 128;

    float c[4][4][4];
    tc_gemm128(g_Ctx, g_Wr + (size_t)3 * Dd * Dd, m0, n0, sm, c);

    const int tid = threadIdx.x;
    const int wid = tid >> 5, lane = tid & 31;
    const int wm = wid & 1, wn = wid >> 1;

#pragma unroll
    for (int mt = 0; mt < 4; mt++) {
#pragma unroll
        for (int h2 = 0; h2 < 2; h2++) {
            const int m = m0 + wm * 64 + mt * 16 + (lane >> 2) + h2 * 8;
#pragma unroll
            for (int nt = 0; nt < 4; nt++) {
                const int col = n0 + wn * 32 + nt * 8 + 2 * (lane & 3);
                float2 v;
                v.x = c[mt][nt][h2 * 2 + 0] + bo[col];
                v.y = c[mt][nt][h2 * 2 + 1] + bo[col + 1];
                *(float2*)&out[(size_t)m * Dd + col] = v;
            }
        }
    }
}

// ===========================================================================
// Flash attention, tf32 mma.sync. Block = 128 q-rows x (head, batch).
// K from g_K [t][hd] rows; V from g_Vt [hd][t] rows — both cp16, no transpose.
// smem: Ks0,Vt0,Ks1,Vt1 (4x16KB) + Ps (128x256B = 32KB) = 96KB.
// ===========================================================================
#define QT 128

__global__ __launch_bounds__(256, 1) void flash_tc_kernel()
{
    extern __shared__ char sm[];
    const uint32_t sb = cvta_smem(sm);
    const uint32_t KsB[2] = { sb, sb + 32768 };
    const uint32_t VtB[2] = { sb + 16384, sb + 49152 };
    const uint32_t Ps = sb + 65536;

    const int tid = threadIdx.x, wid = tid >> 5, lane = tid & 31;
    const int qt = blockIdx.x, h = blockIdx.y, n = blockIdx.z;
    const size_t hoff = (size_t)(n * Hh + h) * Seq * HDim;
    const float* Qg  = g_Q + hoff + (size_t)qt * QT * HDim;
    const float* Kg  = g_K + hoff;
    const float* Vtg = g_Vt + (size_t)(n * Hh + h) * HDim * Seq;

    // ---- Stage Q (128x64) into Ps (rows 256B, 16 units, swizzled), load frags
#pragma unroll
    for (int i = 0; i < 8; i++) {
        int flat = i * 256 + tid;
        int r = flat >> 4, uu = flat & 15;
        float4 v = *(const float4*)(Qg + r * 64 + uu * 4);
        sts_v4(Ps + r * 256 + (((uint32_t)(uu ^ (r & 7))) << 4), v.x, v.y, v.z, v.w);
    }
    __syncthreads();
    const int Rm = wid * 16;
    uint32_t qf[8][4];
#pragma unroll
    for (int s = 0; s < 8; s++) {
        int row = Rm + (lane & 7) + ((lane >> 3) & 1) * 8;
        uint32_t uu = (uint32_t)(2 * s + (lane >> 4));
        ldsm4(Ps + row * 256 + ((uu ^ (uint32_t)(row & 7)) << 4), qf[s]);
    }
    __syncthreads();

    float o[8][4];
#pragma unroll
    for (int nt = 0; nt < 8; nt++)
#pragma unroll
        for (int k = 0; k < 4; k++) o[nt][k] = 0.f;
    float m1 = -1e30f, m2 = -1e30f, l1 = 0.f, l2 = 0.f;

    const int nkt = 2 * qt + 2;

    // issue loads for tile 0 into buffer 0
    {
#pragma unroll
        for (int i = 0; i < 4; i++) {
            int flat = i * 256 + tid;
            int r = flat >> 4, uu = flat & 15;
            uint32_t sw = ((uint32_t)(uu ^ (r & 7))) << 4;
            cp16(KsB[0] + r * 256 + sw, Kg + r * 64 + uu * 4);
            cp16(VtB[0] + r * 256 + sw, Vtg + (size_t)r * Seq + uu * 4);
        }
        CP_COMMIT();
    }

    for (int j = 0; j < nkt; j++) {
        CP_WAIT0();
        __syncthreads();
        const int b = j & 1;
        if (j + 1 < nkt) {
            const float* kg = Kg + (size_t)(j + 1) * 64 * HDim;
            const int tb = (j + 1) * 64;
            const int nb = b ^ 1;
#pragma unroll
            for (int i = 0; i < 4; i++) {
                int flat = i * 256 + tid;
                int r = flat >> 4, uu = flat & 15;
                uint32_t sw = ((uint32_t)(uu ^ (r & 7))) << 4;
                cp16(KsB[nb] + r * 256 + sw, kg + r * 64 + uu * 4);
                cp16(VtB[nb] + r * 256 + sw, Vtg + (size_t)r * Seq + tb + uu * 4);
            }
            CP_COMMIT();
        }

        // ---- S = Q K^T (Q pre-scaled)
        float sfr[8][4];
#pragma unroll
        for (int nt = 0; nt < 8; nt++)
#pragma unroll
            for (int k = 0; k < 4; k++) sfr[nt][k] = 0.f;
#pragma unroll
        for (int sp = 0; sp < 4; sp++) {
#pragma unroll
            for (int nt = 0; nt < 8; nt++) {
                uint32_t bq[4];
                int row = nt * 8 + (lane & 7);
                uint32_t uu = (uint32_t)(sp * 4 + (lane >> 3));
                ldsm4(KsB[b] + row * 256 + ((uu ^ (uint32_t)(row & 7)) << 4), bq);
                mma8(sfr[nt], qf[2 * sp], &bq[0]);
                mma8(sfr[nt], qf[2 * sp + 1], &bq[2]);
            }
        }

        // ---- causal mask (last two kt tiles only)
        const int r1 = qt * QT + Rm + (lane >> 2);
        if (j >= 2 * qt) {
            const int cb = j * 64 + 2 * (lane & 3);
#pragma unroll
            for (int nt = 0; nt < 8; nt++) {
                const int c0 = cb + nt * 8;
                if (c0     > r1)     sfr[nt][0] = -1e30f;
                if (c0 + 1 > r1)     sfr[nt][1] = -1e30f;
                if (c0     > r1 + 8) sfr[nt][2] = -1e30f;
                if (c0 + 1 > r1 + 8) sfr[nt][3] = -1e30f;
            }
        }

        // ---- online softmax
        float mt1 = -1e30f, mt2 = -1e30f;
#pragma unroll
        for (int nt = 0; nt < 8; nt++) {
            mt1 = fmaxf(mt1, fmaxf(sfr[nt][0], sfr[nt][1]));
            mt2 = fmaxf(mt2, fmaxf(sfr[nt][2], sfr[nt][3]));
        }
        mt1 = fmaxf(mt1, __shfl_xor_sync(0xffffffffu, mt1, 1));
        mt1 = fmaxf(mt1, __shfl_xor_sync(0xffffffffu, mt1, 2));
        mt2 = fmaxf(mt2, __shfl_xor_sync(0xffffffffu, mt2, 1));
        mt2 = fmaxf(mt2, __shfl_xor_sync(0xffffffffu, mt2, 2));

        const float mn1 = fmaxf(m1, mt1), al1 = __expf(m1 - mn1);
        const float mn2 = fmaxf(m2, mt2), al2 = __expf(m2 - mn2);
        m1 = mn1; m2 = mn2;
        float rs1 = 0.f, rs2 = 0.f;
#pragma unroll
        for (int nt = 0; nt < 8; nt++) {
            sfr[nt][0] = __expf(sfr[nt][0] - m1); rs1 += sfr[nt][0];
            sfr[nt][1] = __expf(sfr[nt][1] - m1); rs1 += sfr[nt][1];
            sfr[nt][2] = __expf(sfr[nt][2] - m2); rs2 += sfr[nt][2];
            sfr[nt][3] = __expf(sfr[nt][3] - m2); rs2 += sfr[nt][3];
        }
        rs1 += __shfl_xor_sync(0xffffffffu, rs1, 1);
        rs1 += __shfl_xor_sync(0xffffffffu, rs1, 2);
        rs2 += __shfl_xor_sync(0xffffffffu, rs2, 1);
        rs2 += __shfl_xor_sync(0xffffffffu, rs2, 2);
        l1 = l1 * al1 + rs1;
        l2 = l2 * al2 + rs2;
#pragma unroll
        for (int nt = 0; nt < 8; nt++) {
            o[nt][0] *= al1; o[nt][1] *= al1;
            o[nt][2] *= al2; o[nt][3] *= al2;
        }

        // ---- store P (warp-private rows) tf32-rounded
        {
            const int rr1 = Rm + (lane >> 2);
            const int rr2 = rr1 + 8;
#pragma unroll
            for (int nt = 0; nt < 8; nt++) {
                const int c = nt * 8 + 2 * (lane & 3);
                uint32_t a1 = Ps + rr1 * 256 + (((uint32_t)((c >> 2) ^ (rr1 & 7))) << 4) + (c & 3) * 4;
                sts_v2(a1, f2tf(sfr[nt][0]), f2tf(sfr[nt][1]));
                uint32_t a2 = Ps + rr2 * 256 + (((uint32_t)((c >> 2) ^ (rr2 & 7))) << 4) + (c & 3) * 4;
                sts_v2(a2, f2tf(sfr[nt][2]), f2tf(sfr[nt][3]));
            }
        }
        __syncwarp();

        // ---- O += P V  (A = P from Ps, B = Vt rows [hd][t])
#pragma unroll
        for (int sp = 0; sp < 4; sp++) {
            uint32_t a0[4], a1[4];
            {
                int row = Rm + (lane & 7) + ((lane >> 3) & 1) * 8;
                uint32_t uu0 = (uint32_t)(2 * (2 * sp) + (lane >> 4));
                ldsm4(Ps + row * 256 + ((uu0 ^ (uint32_t)(row & 7)) << 4), a0);
                uint32_t uu1 = (uint32_t)(2 * (2 * sp + 1) + (lane >> 4));
                ldsm4(Ps + row * 256 + ((uu1 ^ (uint32_t)(row & 7)) << 4), a1);
            }
#pragma unroll
            for (int nt = 0; nt < 8; nt++) {
                uint32_t bq[4];
                int row = nt * 8 + (lane & 7);
                uint32_t uu = (uint32_t)(sp * 4 + (lane >> 3));
                ldsm4(VtB[b] + row * 256 + ((uu ^ (uint32_t)(row & 7)) << 4), bq);
                mma8(o[nt], a0, &bq[0]);
                mma8(o[nt], a1, &bq[2]);
            }
        }
    }

    // ---- epilogue: normalize, tf32-round, write g_Ctx [N,S,D]
    const float inv1 = 1.f / l1, inv2 = 1.f / l2;
    const int r1g = qt * QT + Rm + (lane >> 2);
    float* C1 = g_Ctx + ((size_t)n * Seq + r1g) * Dd + h * HDim;
    float* C2 = C1 + (size_t)8 * Dd;
#pragma unroll
    for (int nt = 0; nt < 8; nt++) {
        const int c = nt * 8 + 2 * (lane & 3);
        float2 v1, v2;
        v1.x = f2tf(o[nt][0] * inv1); v1.y = f2tf(o[nt][1] * inv1);
        v2.x = f2tf(o[nt][2] * inv2); v2.y = f2tf(o[nt][3] * inv2);
        *(float2*)&C1[c] = v1;
        *(float2*)&C2[c] = v2;
    }
}

// ===========================================================================
extern "C" void kernel_launch(void* const* d_in, const int* in_sizes, int n_in,
                              void* d_out, int out_size)
{
    (void)in_sizes; (void)n_in; (void)out_size;
    const float* X  = (const float*)d_in[0];
    const float* Wq = (const float*)d_in[1];
    const float* bq = (const float*)d_in[2];
    const float* Wk = (const float*)d_in[3];
    const float* bk = (const float*)d_in[4];
    const float* Wv = (const float*)d_in[5];
    const float* bv = (const float*)d_in[6];
    const float* Wo = (const float*)d_in[7];
    const float* bo = (const float*)d_in[8];

    const int gemm_smem  = GNST * GSTAGE;         // 96KB
    const int flash_smem = 4 * 16384 + 32768;     // 96KB
    cudaFuncSetAttribute(qkv_tc_kernel,
                         cudaFuncAttributeMaxDynamicSharedMemorySize, gemm_smem);
    cudaFuncSetAttribute(oproj_tc_kernel,
                         cudaFuncAttributeMaxDynamicSharedMemorySize, gemm_smem);
    cudaFuncSetAttribute(flash_tc_kernel,
                         cudaFuncAttributeMaxDynamicSharedMemorySize, flash_smem);

    round_kernel<<<(2 * (1 << 20)) / 256, 256>>>(X, Wq, Wk, Wv, Wo);

    dim3 gqkv(Dd / 128, (NBatch * Seq) / 128, 3);
    qkv_tc_kernel<<<gqkv, 256, gemm_smem>>>(bq, bk, bv);

    flash_tc_kernel<<<dim3(Seq / QT, Hh, NBatch), 256, flash_smem>>>();

    dim3 go(Dd / 128, (NBatch * Seq) / 128);
    oproj_tc_kernel<<<go, 256, gemm_smem>>>(bo, (float*)d_out);
}

// round 5
// speedup vs baseline: 4.4413x; 1.0921x over previous
#include <cuda_runtime.h>
#include <cstdint>

#define Dd     1024
#define Hh     16
#define HDim   64
#define NBatch 2
#define Seq    2048

// Scratch
__device__ float g_Q  [NBatch * Hh * Seq * HDim];   // [N,H,S,hd], tf32, pre-scaled 0.125
__device__ float g_K  [NBatch * Hh * Seq * HDim];   // [N,H,S,hd], tf32
__device__ float g_Vt [NBatch * Hh * HDim * Seq];   // [N,H,hd,S], tf32 (transposed)
__device__ float g_Ctx[NBatch * Seq * Dd];          // [N,S,D], tf32
__device__ float g_Xr [NBatch * Seq * Dd];          // tf32-rounded X
__device__ float g_Wr [4 * Dd * Dd];                // tf32-rounded Wq,Wk,Wv,Wo

// ===========================================================================
// PTX helpers
// ===========================================================================
__device__ __forceinline__ uint32_t cvta_smem(const void* p) {
    uint32_t a;
    asm("{ .reg .u64 t; cvta.to.shared.u64 t, %1; cvt.u32.u64 %0, t; }"
        : "=r"(a) : "l"(p));
    return a;
}
__device__ __forceinline__ float f2tf(float f) {
    uint32_t u;
    asm("cvt.rna.tf32.f32 %0, %1;" : "=r"(u) : "f"(f));
    return __uint_as_float(u);
}
__device__ __forceinline__ void ldsm4(uint32_t addr, uint32_t* d) {
    asm volatile("ldmatrix.sync.aligned.m8n8.x4.shared.b16 {%0,%1,%2,%3}, [%4];"
                 : "=r"(d[0]), "=r"(d[1]), "=r"(d[2]), "=r"(d[3]) : "r"(addr));
}
__device__ __forceinline__ void mma8(float* c, const uint32_t* a, const uint32_t* b) {
    asm volatile(
        "mma.sync.aligned.m16n8k8.row.col.f32.tf32.tf32.f32 "
        "{%0,%1,%2,%3}, {%4,%5,%6,%7}, {%8,%9}, {%0,%1,%2,%3};"
        : "+f"(c[0]), "+f"(c[1]), "+f"(c[2]), "+f"(c[3])
        : "r"(a[0]), "r"(a[1]), "r"(a[2]), "r"(a[3]), "r"(b[0]), "r"(b[1]));
}
__device__ __forceinline__ void cp16(uint32_t dst, const void* src) {
    asm volatile("cp.async.cg.shared.global [%0], [%1], 16;" :: "r"(dst), "l"(src));
}
#define CP_COMMIT() asm volatile("cp.async.commit_group;" ::: "memory")
#define CP_WAIT0()  asm volatile("cp.async.wait_group 0;" ::: "memory")
#define CP_WAIT1()  asm volatile("cp.async.wait_group 1;" ::: "memory")
__device__ __forceinline__ void sts_v4(uint32_t addr, float x, float y, float z, float w) {
    asm volatile("st.shared.v4.f32 [%0], {%1,%2,%3,%4};"
                 :: "r"(addr), "f"(x), "f"(y), "f"(z), "f"(w) : "memory");
}
__device__ __forceinline__ void sts_v2(uint32_t addr, float x, float y) {
    asm volatile("st.shared.v2.f32 [%0], {%1,%2};"
                 :: "r"(addr), "f"(x), "f"(y) : "memory");
}

// ===========================================================================
// Pre-round: tf32-round X and the 4 weight matrices into scratch (once).
// ===========================================================================
__global__ __launch_bounds__(256) void round_kernel(
    const float* __restrict__ X,
    const float* __restrict__ Wq, const float* __restrict__ Wk,
    const float* __restrict__ Wv, const float* __restrict__ Wo)
{
    const uint32_t u = blockIdx.x * blockDim.x + threadIdx.x;   // float4 unit
    const float4* src;
    float4* dst;
    if (u < (1u << 20)) {
        src = (const float4*)X + u;
        dst = (float4*)g_Xr + u;
    } else {
        uint32_t w = u - (1u << 20);
        uint32_t sel = w >> 18;
        uint32_t off = w & ((1u << 18) - 1);
        const float* Ws = (sel == 0) ? Wq : (sel == 1) ? Wk : (sel == 2) ? Wv : Wo;
        src = (const float4*)Ws + off;
        dst = (float4*)g_Wr + w;
    }
    float4 v = *src;
    v.x = f2tf(v.x); v.y = f2tf(v.y); v.z = f2tf(v.z); v.w = f2tf(v.w);
    *dst = v;
}

// ===========================================================================
// tf32 mma.sync GEMM, cp.async 3-stage pipeline (verified at ~135 TMAC active).
// ===========================================================================
#define GSTAGE 32768
#define GNST   3

__device__ __forceinline__ void gemm_issue_stage(
    const float* __restrict__ A, const float* __restrict__ W,
    int m0, int n0, uint32_t sb, int s, int tid)
{
    const uint32_t buf = sb + (uint32_t)(s % GNST) * GSTAGE;
    const int k0 = s * 32;
#pragma unroll
    for (int i = 0; i < 4; i++) {
        const int flat = i * 256 + tid;
        const int r = flat >> 3, u = flat & 7;
        const uint32_t sw = (uint32_t)(u ^ (r & 7)) << 4;
        cp16(buf + r * 128 + sw,         A + (size_t)(m0 + r) * Dd + k0 + u * 4);
        cp16(buf + 16384 + r * 128 + sw, W + (size_t)(n0 + r) * Dd + k0 + u * 4);
    }
}

__device__ __forceinline__ void tc_gemm128(
    const float* __restrict__ A, const float* __restrict__ W,
    int m0, int n0, char* smem, float c[4][4][4])
{
    const int tid = threadIdx.x;
    const int wid = tid >> 5, lane = tid & 31;
    const int wm = wid & 1, wn = wid >> 1;
    const uint32_t sb = cvta_smem(smem);

#pragma unroll
    for (int mt = 0; mt < 4; mt++)
#pragma unroll
        for (int nt = 0; nt < 4; nt++)
#pragma unroll
            for (int k = 0; k < 4; k++) c[mt][nt][k] = 0.f;

    gemm_issue_stage(A, W, m0, n0, sb, 0, tid); CP_COMMIT();
    gemm_issue_stage(A, W, m0, n0, sb, 1, tid); CP_COMMIT();

    for (int k = 0; k < 32; k++) {
        CP_WAIT1();
        __syncthreads();
        if (k + 2 < 32) gemm_issue_stage(A, W, m0, n0, sb, k + 2, tid);
        CP_COMMIT();

        const uint32_t cur = sb + (uint32_t)(k % GNST) * GSTAGE;
        const uint32_t Ab = cur, Bb = cur + 16384;
#pragma unroll
        for (int sp = 0; sp < 2; sp++) {
            uint32_t bq[4][4];
#pragma unroll
            for (int nt = 0; nt < 4; nt++) {
                int row = wn * 32 + nt * 8 + (lane & 7);
                uint32_t uu = (uint32_t)(sp * 4 + (lane >> 3));
                ldsm4(Bb + row * 128 + ((uu ^ (uint32_t)(row & 7)) << 4), bq[nt]);
            }
#pragma unroll
            for (int sh = 0; sh < 2; sh++) {
                const int s = sp * 2 + sh;
                uint32_t aq[4][4];
#pragma unroll
                for (int mt = 0; mt < 4; mt++) {
                    int row = wm * 64 + mt * 16 + (lane & 7) + ((lane >> 3) & 1) * 8;
                    uint32_t uu = (uint32_t)(2 * s + (lane >> 4));
                    ldsm4(Ab + row * 128 + ((uu ^ (uint32_t)(row & 7)) << 4), aq[mt]);
                }
#pragma unroll
                for (int mt = 0; mt < 4; mt++)
#pragma unroll
                    for (int nt = 0; nt < 4; nt++)
                        mma8(c[mt][nt], aq[mt], &bq[nt][sh * 2]);
            }
        }
    }
}

// ===========================================================================
// QKV projection: z = 0/1/2 -> Q/K/V.
// ===========================================================================
__global__ __launch_bounds__(256, 2)
void qkv_tc_kernel(const float* __restrict__ bq, const float* __restrict__ bk,
                   const float* __restrict__ bv)
{
    extern __shared__ char sm[];
    const int z = blockIdx.z;
    const float* W    = g_Wr + (size_t)z * Dd * Dd;
    const float* bias = (z == 0) ? bq : (z == 1) ? bk : bv;

    const int m0 = blockIdx.y * 128;
    const int n0 = blockIdx.x * 128;

    float c[4][4][4];
    tc_gemm128(g_Xr, W, m0, n0, sm, c);

    const int tid = threadIdx.x;
    const int wid = tid >> 5, lane = tid & 31;
    const int wm = wid & 1, wn = wid >> 1;
    const float scl = (z == 0) ? 0.125f : 1.0f;

    if (z < 2) {
        float* dst = (z == 0) ? g_Q : g_K;
#pragma unroll
        for (int mt = 0; mt < 4; mt++) {
#pragma unroll
            for (int h2 = 0; h2 < 2; h2++) {
                const int m = m0 + wm * 64 + mt * 16 + (lane >> 2) + h2 * 8;
                const int b = m >> 11;
                const int s = m & (Seq - 1);
#pragma unroll
                for (int nt = 0; nt < 4; nt++) {
                    const int col = n0 + wn * 32 + nt * 8 + 2 * (lane & 3);
                    const int hh = col >> 6, hd = col & 63;
                    float2 v;
                    v.x = f2tf((c[mt][nt][h2 * 2 + 0] + bias[col]) * scl);
                    v.y = f2tf((c[mt][nt][h2 * 2 + 1] + bias[col + 1]) * scl);
                    *(float2*)&dst[((size_t)(b * Hh + hh) * Seq + s) * HDim + hd] = v;
                }
            }
        }
    } else {
#pragma unroll
        for (int mt = 0; mt < 4; mt++) {
#pragma unroll
            for (int h2 = 0; h2 < 2; h2++) {
                const int m = m0 + wm * 64 + mt * 16 + (lane >> 2) + h2 * 8;
                const int b = m >> 11;
                const int s = m & (Seq - 1);
#pragma unroll
                for (int nt = 0; nt < 4; nt++) {
                    const int col = n0 + wn * 32 + nt * 8 + 2 * (lane & 3);
                    const int hh = col >> 6, hd = col & 63;
                    float* dp = g_Vt + ((size_t)(b * Hh + hh) * HDim + hd) * Seq + s;
                    dp[0]   = f2tf(c[mt][nt][h2 * 2 + 0] + bias[col]);
                    dp[Seq] = f2tf(c[mt][nt][h2 * 2 + 1] + bias[col + 1]);
                }
            }
        }
    }
}

// ===========================================================================
// Output projection
// ===========================================================================
__global__ __launch_bounds__(256, 2)
void oproj_tc_kernel(const float* __restrict__ bo, float* __restrict__ out)
{
    extern __shared__ char sm[];
    const int m0 = blockIdx.y * 128;
    const int n0 = blockIdx.x * 128;

    float c[4][4][4];
    tc_gemm128(g_Ctx, g_Wr + (size_t)3 * Dd * Dd, m0, n0, sm, c);

    const int tid = threadIdx.x;
    const int wid = tid >> 5, lane = tid & 31;
    const int wm = wid & 1, wn = wid >> 1;

#pragma unroll
    for (int mt = 0; mt < 4; mt++) {
#pragma unroll
        for (int h2 = 0; h2 < 2; h2++) {
            const int m = m0 + wm * 64 + mt * 16 + (lane >> 2) + h2 * 8;
#pragma unroll
            for (int nt = 0; nt < 4; nt++) {
                const int col = n0 + wn * 32 + nt * 8 + 2 * (lane & 3);
                float2 v;
                v.x = c[mt][nt][h2 * 2 + 0] + bo[col];
                v.y = c[mt][nt][h2 * 2 + 1] + bo[col + 1];
                *(float2*)&out[(size_t)m * Dd + col] = v;
            }
        }
    }
}

// ===========================================================================
// Flash attention, tf32 mma.sync. 2 CTAs/SM (reg-clamped) so one CTA's
// softmax (MUFU) overlaps the other's HMMA. LPT: big-qt blocks first.
// ===========================================================================
#define QT 128

__global__ __launch_bounds__(256, 2) void flash_tc_kernel()
{
    extern __shared__ char sm[];
    const uint32_t sb = cvta_smem(sm);
    const uint32_t KsB[2] = { sb, sb + 32768 };
    const uint32_t VtB[2] = { sb + 16384, sb + 49152 };
    const uint32_t Ps = sb + 65536;

    const int tid = threadIdx.x, wid = tid >> 5, lane = tid & 31;
    const int qt = (int)gridDim.x - 1 - (int)blockIdx.x;    // LPT: large qt first
    const int h = blockIdx.y, n = blockIdx.z;
    const size_t hoff = (size_t)(n * Hh + h) * Seq * HDim;
    const float* Qg  = g_Q + hoff + (size_t)qt * QT * HDim;
    const float* Kg  = g_K + hoff;
    const float* Vtg = g_Vt + (size_t)(n * Hh + h) * HDim * Seq;

    // ---- Stage Q (128x64) into Ps (rows 256B, swizzled), load fragments
#pragma unroll
    for (int i = 0; i < 8; i++) {
        int flat = i * 256 + tid;
        int r = flat >> 4, uu = flat & 15;
        float4 v = *(const float4*)(Qg + r * 64 + uu * 4);
        sts_v4(Ps + r * 256 + (((uint32_t)(uu ^ (r & 7))) << 4), v.x, v.y, v.z, v.w);
    }
    __syncthreads();
    const int Rm = wid * 16;
    uint32_t qf[8][4];
#pragma unroll
    for (int s = 0; s < 8; s++) {
        int row = Rm + (lane & 7) + ((lane >> 3) & 1) * 8;
        uint32_t uu = (uint32_t)(2 * s + (lane >> 4));
        ldsm4(Ps + row * 256 + ((uu ^ (uint32_t)(row & 7)) << 4), qf[s]);
    }
    __syncthreads();

    float o[8][4];
#pragma unroll
    for (int nt = 0; nt < 8; nt++)
#pragma unroll
        for (int k = 0; k < 4; k++) o[nt][k] = 0.f;
    float m1 = -1e30f, m2 = -1e30f, l1 = 0.f, l2 = 0.f;

    const int nkt = 2 * qt + 2;

    {
#pragma unroll
        for (int i = 0; i < 4; i++) {
            int flat = i * 256 + tid;
            int r = flat >> 4, uu = flat & 15;
            uint32_t sw = ((uint32_t)(uu ^ (r & 7))) << 4;
            cp16(KsB[0] + r * 256 + sw, Kg + r * 64 + uu * 4);
            cp16(VtB[0] + r * 256 + sw, Vtg + (size_t)r * Seq + uu * 4);
        }
        CP_COMMIT();
    }

    for (int j = 0; j < nkt; j++) {
        CP_WAIT0();
        __syncthreads();
        const int b = j & 1;
        if (j + 1 < nkt) {
            const float* kg = Kg + (size_t)(j + 1) * 64 * HDim;
            const int tb = (j + 1) * 64;
            const int nb = b ^ 1;
#pragma unroll
            for (int i = 0; i < 4; i++) {
                int flat = i * 256 + tid;
                int r = flat >> 4, uu = flat & 15;
                uint32_t sw = ((uint32_t)(uu ^ (r & 7))) << 4;
                cp16(KsB[nb] + r * 256 + sw, kg + r * 64 + uu * 4);
                cp16(VtB[nb] + r * 256 + sw, Vtg + (size_t)r * Seq + tb + uu * 4);
            }
            CP_COMMIT();
        }

        // ---- S = Q K^T (Q pre-scaled)
        float sfr[8][4];
#pragma unroll
        for (int nt = 0; nt < 8; nt++)
#pragma unroll
            for (int k = 0; k < 4; k++) sfr[nt][k] = 0.f;
#pragma unroll
        for (int sp = 0; sp < 4; sp++) {
#pragma unroll
            for (int nt = 0; nt < 8; nt++) {
                uint32_t bq[4];
                int row = nt * 8 + (lane & 7);
                uint32_t uu = (uint32_t)(sp * 4 + (lane >> 3));
                ldsm4(KsB[b] + row * 256 + ((uu ^ (uint32_t)(row & 7)) << 4), bq);
                mma8(sfr[nt], qf[2 * sp], &bq[0]);
                mma8(sfr[nt], qf[2 * sp + 1], &bq[2]);
            }
        }

        // ---- causal mask (last two kt tiles only)
        const int r1 = qt * QT + Rm + (lane >> 2);
        if (j >= 2 * qt) {
            const int cb = j * 64 + 2 * (lane & 3);
#pragma unroll
            for (int nt = 0; nt < 8; nt++) {
                const int c0 = cb + nt * 8;
                if (c0     > r1)     sfr[nt][0] = -1e30f;
                if (c0 + 1 > r1)     sfr[nt][1] = -1e30f;
                if (c0     > r1 + 8) sfr[nt][2] = -1e30f;
                if (c0 + 1 > r1 + 8) sfr[nt][3] = -1e30f;
            }
        }

        // ---- online softmax
        float mt1 = -1e30f, mt2 = -1e30f;
#pragma unroll
        for (int nt = 0; nt < 8; nt++) {
            mt1 = fmaxf(mt1, fmaxf(sfr[nt][0], sfr[nt][1]));
            mt2 = fmaxf(mt2, fmaxf(sfr[nt][2], sfr[nt][3]));
        }
        mt1 = fmaxf(mt1, __shfl_xor_sync(0xffffffffu, mt1, 1));
        mt1 = fmaxf(mt1, __shfl_xor_sync(0xffffffffu, mt1, 2));
        mt2 = fmaxf(mt2, __shfl_xor_sync(0xffffffffu, mt2, 1));
        mt2 = fmaxf(mt2, __shfl_xor_sync(0xffffffffu, mt2, 2));

        const float mn1 = fmaxf(m1, mt1), al1 = __expf(m1 - mn1);
        const float mn2 = fmaxf(m2, mt2), al2 = __expf(m2 - mn2);
        m1 = mn1; m2 = mn2;
        float rs1 = 0.f, rs2 = 0.f;
#pragma unroll
        for (int nt = 0; nt < 8; nt++) {
            sfr[nt][0] = __expf(sfr[nt][0] - m1); rs1 += sfr[nt][0];
            sfr[nt][1] = __expf(sfr[nt][1] - m1); rs1 += sfr[nt][1];
            sfr[nt][2] = __expf(sfr[nt][2] - m2); rs2 += sfr[nt][2];
            sfr[nt][3] = __expf(sfr[nt][3] - m2); rs2 += sfr[nt][3];
        }
        rs1 += __shfl_xor_sync(0xffffffffu, rs1, 1);
        rs1 += __shfl_xor_sync(0xffffffffu, rs1, 2);
        rs2 += __shfl_xor_sync(0xffffffffu, rs2, 1);
        rs2 += __shfl_xor_sync(0xffffffffu, rs2, 2);
        l1 = l1 * al1 + rs1;
        l2 = l2 * al2 + rs2;
#pragma unroll
        for (int nt = 0; nt < 8; nt++) {
            o[nt][0] *= al1; o[nt][1] *= al1;
            o[nt][2] *= al2; o[nt][3] *= al2;
        }

        // ---- store P (warp-private rows) tf32-rounded
        {
            const int rr1 = Rm + (lane >> 2);
            const int rr2 = rr1 + 8;
#pragma unroll
            for (int nt = 0; nt < 8; nt++) {
                const int c = nt * 8 + 2 * (lane & 3);
                uint32_t a1 = Ps + rr1 * 256 + (((uint32_t)((c >> 2) ^ (rr1 & 7))) << 4) + (c & 3) * 4;
                sts_v2(a1, f2tf(sfr[nt][0]), f2tf(sfr[nt][1]));
                uint32_t a2 = Ps + rr2 * 256 + (((uint32_t)((c >> 2) ^ (rr2 & 7))) << 4) + (c & 3) * 4;
                sts_v2(a2, f2tf(sfr[nt][2]), f2tf(sfr[nt][3]));
            }
        }
        __syncwarp();

        // ---- O += P V
#pragma unroll
        for (int sp = 0; sp < 4; sp++) {
            uint32_t a0[4], a1[4];
            {
                int row = Rm + (lane & 7) + ((lane >> 3) & 1) * 8;
                uint32_t uu0 = (uint32_t)(2 * (2 * sp) + (lane >> 4));
                ldsm4(Ps + row * 256 + ((uu0 ^ (uint32_t)(row & 7)) << 4), a0);
                uint32_t uu1 = (uint32_t)(2 * (2 * sp + 1) + (lane >> 4));
                ldsm4(Ps + row * 256 + ((uu1 ^ (uint32_t)(row & 7)) << 4), a1);
            }
#pragma unroll
            for (int nt = 0; nt < 8; nt++) {
                uint32_t bq[4];
                int row = nt * 8 + (lane & 7);
                uint32_t uu = (uint32_t)(sp * 4 + (lane >> 3));
                ldsm4(VtB[b] + row * 256 + ((uu ^ (uint32_t)(row & 7)) << 4), bq);
                mma8(o[nt], a0, &bq[0]);
                mma8(o[nt], a1, &bq[2]);
            }
        }
    }

    // ---- epilogue: normalize, tf32-round, write g_Ctx [N,S,D]
    const float inv1 = 1.f / l1, inv2 = 1.f / l2;
    const int r1g = qt * QT + Rm + (lane >> 2);
    float* C1 = g_Ctx + ((size_t)n * Seq + r1g) * Dd + h * HDim;
    float* C2 = C1 + (size_t)8 * Dd;
#pragma unroll
    for (int nt = 0; nt < 8; nt++) {
        const int c = nt * 8 + 2 * (lane & 3);
        float2 v1, v2;
        v1.x = f2tf(o[nt][0] * inv1); v1.y = f2tf(o[nt][1] * inv1);
        v2.x = f2tf(o[nt][2] * inv2); v2.y = f2tf(o[nt][3] * inv2);
        *(float2*)&C1[c] = v1;
        *(float2*)&C2[c] = v2;
    }
}

// ===========================================================================
extern "C" void kernel_launch(void* const* d_in, const int* in_sizes, int n_in,
                              void* d_out, int out_size)
{
    (void)in_sizes; (void)n_in; (void)out_size;
    const float* X  = (const float*)d_in[0];
    const float* Wq = (const float*)d_in[1];
    const float* bq = (const float*)d_in[2];
    const float* Wk = (const float*)d_in[3];
    const float* bk = (const float*)d_in[4];
    const float* Wv = (const float*)d_in[5];
    const float* bv = (const float*)d_in[6];
    const float* Wo = (const float*)d_in[7];
    const float* bo = (const float*)d_in[8];

    const int gemm_smem  = GNST * GSTAGE;         // 96KB
    const int flash_smem = 4 * 16384 + 32768;     // 96KB
    cudaFuncSetAttribute(qkv_tc_kernel,
                         cudaFuncAttributeMaxDynamicSharedMemorySize, gemm_smem);
    cudaFuncSetAttribute(oproj_tc_kernel,
                         cudaFuncAttributeMaxDynamicSharedMemorySize, gemm_smem);
    cudaFuncSetAttribute(flash_tc_kernel,
                         cudaFuncAttributeMaxDynamicSharedMemorySize, flash_smem);

    round_kernel<<<(2 * (1 << 20)) / 256, 256>>>(X, Wq, Wk, Wv, Wo);

    dim3 gqkv(Dd / 128, (NBatch * Seq) / 128, 3);
    qkv_tc_kernel<<<gqkv, 256, gemm_smem>>>(bq, bk, bv);

    flash_tc_kernel<<<dim3(Seq / QT, Hh, NBatch), 256, flash_smem>>>();

    dim3 go(Dd / 128, (NBatch * Seq) / 128);
    oproj_tc_kernel<<<go, 256, gemm_smem>>>(bo, (float*)d_out);
}

// round 6
// speedup vs baseline: 4.4708x; 1.0066x over previous
#include <cuda_runtime.h>
#include <cstdint>

#define Dd     1024
#define Hh     16
#define HDim   64
#define NBatch 2
#define Seq    2048

// Scratch
__device__ float g_Q  [NBatch * Hh * Seq * HDim];   // [N,H,S,hd], tf32, pre-scaled 0.125
__device__ float g_K  [NBatch * Hh * Seq * HDim];   // [N,H,S,hd], tf32
__device__ float g_Vt [NBatch * Hh * HDim * Seq];   // [N,H,hd,S], tf32 (transposed)
__device__ float g_Ctx[NBatch * Seq * Dd];          // [N,S,D], tf32
__device__ float g_Xr [NBatch * Seq * Dd];          // tf32-rounded X
__device__ float g_Wr [4 * Dd * Dd];                // tf32-rounded Wq,Wk,Wv,Wo

// ===========================================================================
// PTX helpers
// ===========================================================================
__device__ __forceinline__ uint32_t cvta_smem(const void* p) {
    uint32_t a;
    asm("{ .reg .u64 t; cvta.to.shared.u64 t, %1; cvt.u32.u64 %0, t; }"
        : "=r"(a) : "l"(p));
    return a;
}
__device__ __forceinline__ float f2tf(float f) {
    uint32_t u;
    asm("cvt.rna.tf32.f32 %0, %1;" : "=r"(u) : "f"(f));
    return __uint_as_float(u);
}
__device__ __forceinline__ void ldsm4(uint32_t addr, uint32_t* d) {
    asm volatile("ldmatrix.sync.aligned.m8n8.x4.shared.b16 {%0,%1,%2,%3}, [%4];"
                 : "=r"(d[0]), "=r"(d[1]), "=r"(d[2]), "=r"(d[3]) : "r"(addr));
}
__device__ __forceinline__ void mma8(float* c, const uint32_t* a, const uint32_t* b) {
    asm volatile(
        "mma.sync.aligned.m16n8k8.row.col.f32.tf32.tf32.f32 "
        "{%0,%1,%2,%3}, {%4,%5,%6,%7}, {%8,%9}, {%0,%1,%2,%3};"
        : "+f"(c[0]), "+f"(c[1]), "+f"(c[2]), "+f"(c[3])
        : "r"(a[0]), "r"(a[1]), "r"(a[2]), "r"(a[3]), "r"(b[0]), "r"(b[1]));
}
__device__ __forceinline__ void cp16(uint32_t dst, const void* src) {
    asm volatile("cp.async.cg.shared.global [%0], [%1], 16;" :: "r"(dst), "l"(src));
}
#define CP_COMMIT() asm volatile("cp.async.commit_group;" ::: "memory")
#define CP_WAIT0()  asm volatile("cp.async.wait_group 0;" ::: "memory")
#define CP_WAIT1()  asm volatile("cp.async.wait_group 1;" ::: "memory")
__device__ __forceinline__ void sts_v4(uint32_t addr, float x, float y, float z, float w) {
    asm volatile("st.shared.v4.f32 [%0], {%1,%2,%3,%4};"
                 :: "r"(addr), "f"(x), "f"(y), "f"(z), "f"(w) : "memory");
}
__device__ __forceinline__ void sts_v2(uint32_t addr, float x, float y) {
    asm volatile("st.shared.v2.f32 [%0], {%1,%2};"
                 :: "r"(addr), "f"(x), "f"(y) : "memory");
}

// ===========================================================================
// Pre-round: tf32-round X and the 4 weight matrices into scratch (once).
// ===========================================================================
__global__ __launch_bounds__(256) void round_kernel(
    const float* __restrict__ X,
    const float* __restrict__ Wq, const float* __restrict__ Wk,
    const float* __restrict__ Wv, const float* __restrict__ Wo)
{
    const uint32_t u = blockIdx.x * blockDim.x + threadIdx.x;   // float4 unit
    const float4* src;
    float4* dst;
    if (u < (1u << 20)) {
        src = (const float4*)X + u;
        dst = (float4*)g_Xr + u;
    } else {
        uint32_t w = u - (1u << 20);
        uint32_t sel = w >> 18;
        uint32_t off = w & ((1u << 18) - 1);
        const float* Ws = (sel == 0) ? Wq : (sel == 1) ? Wk : (sel == 2) ? Wv : Wo;
        src = (const float4*)Ws + off;
        dst = (float4*)g_Wr + w;
    }
    float4 v = *src;
    v.x = f2tf(v.x); v.y = f2tf(v.y); v.z = f2tf(v.z); v.w = f2tf(v.w);
    *dst = v;
}

// ===========================================================================
// tf32 mma.sync GEMM, cp.async 3-stage pipeline (verified at ~135 TMAC active).
// ===========================================================================
#define GSTAGE 32768
#define GNST   3

__device__ __forceinline__ void gemm_issue_stage(
    const float* __restrict__ A, const float* __restrict__ W,
    int m0, int n0, uint32_t sb, int s, int tid)
{
    const uint32_t buf = sb + (uint32_t)(s % GNST) * GSTAGE;
    const int k0 = s * 32;
#pragma unroll
    for (int i = 0; i < 4; i++) {
        const int flat = i * 256 + tid;
        const int r = flat >> 3, u = flat & 7;
        const uint32_t sw = (uint32_t)(u ^ (r & 7)) << 4;
        cp16(buf + r * 128 + sw,         A + (size_t)(m0 + r) * Dd + k0 + u * 4);
        cp16(buf + 16384 + r * 128 + sw, W + (size_t)(n0 + r) * Dd + k0 + u * 4);
    }
}

__device__ __forceinline__ void tc_gemm128(
    const float* __restrict__ A, const float* __restrict__ W,
    int m0, int n0, char* smem, float c[4][4][4])
{
    const int tid = threadIdx.x;
    const int wid = tid >> 5, lane = tid & 31;
    const int wm = wid & 1, wn = wid >> 1;
    const uint32_t sb = cvta_smem(smem);

#pragma unroll
    for (int mt = 0; mt < 4; mt++)
#pragma unroll
        for (int nt = 0; nt < 4; nt++)
#pragma unroll
            for (int k = 0; k < 4; k++) c[mt][nt][k] = 0.f;

    gemm_issue_stage(A, W, m0, n0, sb, 0, tid); CP_COMMIT();
    gemm_issue_stage(A, W, m0, n0, sb, 1, tid); CP_COMMIT();

    for (int k = 0; k < 32; k++) {
        CP_WAIT1();
        __syncthreads();
        if (k + 2 < 32) gemm_issue_stage(A, W, m0, n0, sb, k + 2, tid);
        CP_COMMIT();

        const uint32_t cur = sb + (uint32_t)(k % GNST) * GSTAGE;
        const uint32_t Ab = cur, Bb = cur + 16384;
#pragma unroll
        for (int sp = 0; sp < 2; sp++) {
            uint32_t bq[4][4];
#pragma unroll
            for (int nt = 0; nt < 4; nt++) {
                int row = wn * 32 + nt * 8 + (lane & 7);
                uint32_t uu = (uint32_t)(sp * 4 + (lane >> 3));
                ldsm4(Bb + row * 128 + ((uu ^ (uint32_t)(row & 7)) << 4), bq[nt]);
            }
#pragma unroll
            for (int sh = 0; sh < 2; sh++) {
                const int s = sp * 2 + sh;
                uint32_t aq[4][4];
#pragma unroll
                for (int mt = 0; mt < 4; mt++) {
                    int row = wm * 64 + mt * 16 + (lane & 7) + ((lane >> 3) & 1) * 8;
                    uint32_t uu = (uint32_t)(2 * s + (lane >> 4));
                    ldsm4(Ab + row * 128 + ((uu ^ (uint32_t)(row & 7)) << 4), aq[mt]);
                }
#pragma unroll
                for (int mt = 0; mt < 4; mt++)
#pragma unroll
                    for (int nt = 0; nt < 4; nt++)
                        mma8(c[mt][nt], aq[mt], &bq[nt][sh * 2]);
            }
        }
    }
}

// ===========================================================================
// QKV projection: z = 0/1/2 -> Q/K/V.
// ===========================================================================
__global__ __launch_bounds__(256, 2)
void qkv_tc_kernel(const float* __restrict__ bq, const float* __restrict__ bk,
                   const float* __restrict__ bv)
{
    extern __shared__ char sm[];
    const int z = blockIdx.z;
    const float* W    = g_Wr + (size_t)z * Dd * Dd;
    const float* bias = (z == 0) ? bq : (z == 1) ? bk : bv;

    const int m0 = blockIdx.y * 128;
    const int n0 = blockIdx.x * 128;

    float c[4][4][4];
    tc_gemm128(g_Xr, W, m0, n0, sm, c);

    const int tid = threadIdx.x;
    const int wid = tid >> 5, lane = tid & 31;
    const int wm = wid & 1, wn = wid >> 1;
    const float scl = (z == 0) ? 0.125f : 1.0f;

    if (z < 2) {
        float* dst = (z == 0) ? g_Q : g_K;
#pragma unroll
        for (int mt = 0; mt < 4; mt++) {
#pragma unroll
            for (int h2 = 0; h2 < 2; h2++) {
                const int m = m0 + wm * 64 + mt * 16 + (lane >> 2) + h2 * 8;
                const int b = m >> 11;
                const int s = m & (Seq - 1);
#pragma unroll
                for (int nt = 0; nt < 4; nt++) {
                    const int col = n0 + wn * 32 + nt * 8 + 2 * (lane & 3);
                    const int hh = col >> 6, hd = col & 63;
                    float2 v;
                    v.x = f2tf((c[mt][nt][h2 * 2 + 0] + bias[col]) * scl);
                    v.y = f2tf((c[mt][nt][h2 * 2 + 1] + bias[col + 1]) * scl);
                    *(float2*)&dst[((size_t)(b * Hh + hh) * Seq + s) * HDim + hd] = v;
                }
            }
        }
    } else {
#pragma unroll
        for (int mt = 0; mt < 4; mt++) {
#pragma unroll
            for (int h2 = 0; h2 < 2; h2++) {
                const int m = m0 + wm * 64 + mt * 16 + (lane >> 2) + h2 * 8;
                const int b = m >> 11;
                const int s = m & (Seq - 1);
#pragma unroll
                for (int nt = 0; nt < 4; nt++) {
                    const int col = n0 + wn * 32 + nt * 8 + 2 * (lane & 3);
                    const int hh = col >> 6, hd = col & 63;
                    float* dp = g_Vt + ((size_t)(b * Hh + hh) * HDim + hd) * Seq + s;
                    dp[0]   = f2tf(c[mt][nt][h2 * 2 + 0] + bias[col]);
                    dp[Seq] = f2tf(c[mt][nt][h2 * 2 + 1] + bias[col + 1]);
                }
            }
        }
    }
}

// ===========================================================================
// Output projection
// ===========================================================================
__global__ __launch_bounds__(256, 2)
void oproj_tc_kernel(const float* __restrict__ bo, float* __restrict__ out)
{
    extern __shared__ char sm[];
    const int m0 = blockIdx.y * 128;
    const int n0 = blockIdx.x * 128;

    float c[4][4][4];
    tc_gemm128(g_Ctx, g_Wr + (size_t)3 * Dd * Dd, m0, n0, sm, c);

    const int tid = threadIdx.x;
    const int wid = tid >> 5, lane = tid & 31;
    const int wm = wid & 1, wn = wid >> 1;

#pragma unroll
    for (int mt = 0; mt < 4; mt++) {
#pragma unroll
        for (int h2 = 0; h2 < 2; h2++) {
            const int m = m0 + wm * 64 + mt * 16 + (lane >> 2) + h2 * 8;
#pragma unroll
            for (int nt = 0; nt < 4; nt++) {
                const int col = n0 + wn * 32 + nt * 8 + 2 * (lane & 3);
                float2 v;
                v.x = c[mt][nt][h2 * 2 + 0] + bo[col];
                v.y = c[mt][nt][h2 * 2 + 1] + bo[col + 1];
                *(float2*)&out[(size_t)m * Dd + col] = v;
            }
        }
    }
}

// ===========================================================================
// Flash attention, tf32 mma.sync. 2 CTAs/SM (reg-clamped) so one CTA's
// softmax (MUFU) overlaps the other's HMMA. LPT: big-qt blocks first.
// ===========================================================================
#define QT 128

__global__ __launch_bounds__(256, 2) void flash_tc_kernel()
{
    extern __shared__ char sm[];
    const uint32_t sb = cvta_smem(sm);
    const uint32_t KsB[2] = { sb, sb + 32768 };
    const uint32_t VtB[2] = { sb + 16384, sb + 49152 };
    const uint32_t Ps = sb + 65536;

    const int tid = threadIdx.x, wid = tid >> 5, lane = tid & 31;
    const int qt = (int)gridDim.x - 1 - (int)blockIdx.x;    // LPT: large qt first
    const int h = blockIdx.y, n = blockIdx.z;
    const size_t hoff = (size_t)(n * Hh + h) * Seq * HDim;
    const float* Qg  = g_Q + hoff + (size_t)qt * QT * HDim;
    const float* Kg  = g_K + hoff;
    const float* Vtg = g_Vt + (size_t)(n * Hh + h) * HDim * Seq;

    // ---- Stage Q (128x64) into Ps (rows 256B, swizzled), load fragments
#pragma unroll
    for (int i = 0; i < 8; i++) {
        int flat = i * 256 + tid;
        int r = flat >> 4, uu = flat & 15;
        float4 v = *(const float4*)(Qg + r * 64 + uu * 4);
        sts_v4(Ps + r * 256 + (((uint32_t)(uu ^ (r & 7))) << 4), v.x, v.y, v.z, v.w);
    }
    __syncthreads();
    const int Rm = wid * 16;
    uint32_t qf[8][4];
#pragma unroll
    for (int s = 0; s < 8; s++) {
        int row = Rm + (lane & 7) + ((lane >> 3) & 1) * 8;
        uint32_t uu = (uint32_t)(2 * s + (lane >> 4));
        ldsm4(Ps + row * 256 + ((uu ^ (uint32_t)(row & 7)) << 4), qf[s]);
    }
    __syncthreads();

    float o[8][4];
#pragma unroll
    for (int nt = 0; nt < 8; nt++)
#pragma unroll
        for (int k = 0; k < 4; k++) o[nt][k] = 0.f;
    float m1 = -1e30f, m2 = -1e30f, l1 = 0.f, l2 = 0.f;

    const int nkt = 2 * qt + 2;

    {
#pragma unroll
        for (int i = 0; i < 4; i++) {
            int flat = i * 256 + tid;
            int r = flat >> 4, uu = flat & 15;
            uint32_t sw = ((uint32_t)(uu ^ (r & 7))) << 4;
            cp16(KsB[0] + r * 256 + sw, Kg + r * 64 + uu * 4);
            cp16(VtB[0] + r * 256 + sw, Vtg + (size_t)r * Seq + uu * 4);
        }
        CP_COMMIT();
    }

    for (int j = 0; j < nkt; j++) {
        CP_WAIT0();
        __syncthreads();
        const int b = j & 1;
        if (j + 1 < nkt) {
            const float* kg = Kg + (size_t)(j + 1) * 64 * HDim;
            const int tb = (j + 1) * 64;
            const int nb = b ^ 1;
#pragma unroll
            for (int i = 0; i < 4; i++) {
                int flat = i * 256 + tid;
                int r = flat >> 4, uu = flat & 15;
                uint32_t sw = ((uint32_t)(uu ^ (r & 7))) << 4;
                cp16(KsB[nb] + r * 256 + sw, kg + r * 64 + uu * 4);
                cp16(VtB[nb] + r * 256 + sw, Vtg + (size_t)r * Seq + tb + uu * 4);
            }
            CP_COMMIT();
        }

        // ---- S = Q K^T (Q pre-scaled)
        float sfr[8][4];
#pragma unroll
        for (int nt = 0; nt < 8; nt++)
#pragma unroll
            for (int k = 0; k < 4; k++) sfr[nt][k] = 0.f;
#pragma unroll
        for (int sp = 0; sp < 4; sp++) {
#pragma unroll
            for (int nt = 0; nt < 8; nt++) {
                uint32_t bq[4];
                int row = nt * 8 + (lane & 7);
                uint32_t uu = (uint32_t)(sp * 4 + (lane >> 3));
                ldsm4(KsB[b] + row * 256 + ((uu ^ (uint32_t)(row & 7)) << 4), bq);
                mma8(sfr[nt], qf[2 * sp], &bq[0]);
                mma8(sfr[nt], qf[2 * sp + 1], &bq[2]);
            }
        }

        // ---- causal mask (last two kt tiles only)
        const int r1 = qt * QT + Rm + (lane >> 2);
        if (j >= 2 * qt) {
            const int cb = j * 64 + 2 * (lane & 3);
#pragma unroll
            for (int nt = 0; nt < 8; nt++) {
                const int c0 = cb + nt * 8;
                if (c0     > r1)     sfr[nt][0] = -1e30f;
                if (c0 + 1 > r1)     sfr[nt][1] = -1e30f;
                if (c0     > r1 + 8) sfr[nt][2] = -1e30f;
                if (c0 + 1 > r1 + 8) sfr[nt][3] = -1e30f;
            }
        }

        // ---- online softmax
        float mt1 = -1e30f, mt2 = -1e30f;
#pragma unroll
        for (int nt = 0; nt < 8; nt++) {
            mt1 = fmaxf(mt1, fmaxf(sfr[nt][0], sfr[nt][1]));
            mt2 = fmaxf(mt2, fmaxf(sfr[nt][2], sfr[nt][3]));
        }
        mt1 = fmaxf(mt1, __shfl_xor_sync(0xffffffffu, mt1, 1));
        mt1 = fmaxf(mt1, __shfl_xor_sync(0xffffffffu, mt1, 2));
        mt2 = fmaxf(mt2, __shfl_xor_sync(0xffffffffu, mt2, 1));
        mt2 = fmaxf(mt2, __shfl_xor_sync(0xffffffffu, mt2, 2));

        const float mn1 = fmaxf(m1, mt1), al1 = __expf(m1 - mn1);
        const float mn2 = fmaxf(m2, mt2), al2 = __expf(m2 - mn2);
        m1 = mn1; m2 = mn2;
        float rs1 = 0.f, rs2 = 0.f;
#pragma unroll
        for (int nt = 0; nt < 8; nt++) {
            sfr[nt][0] = __expf(sfr[nt][0] - m1); rs1 += sfr[nt][0];
            sfr[nt][1] = __expf(sfr[nt][1] - m1); rs1 += sfr[nt][1];
            sfr[nt][2] = __expf(sfr[nt][2] - m2); rs2 += sfr[nt][2];
            sfr[nt][3] = __expf(sfr[nt][3] - m2); rs2 += sfr[nt][3];
        }
        rs1 += __shfl_xor_sync(0xffffffffu, rs1, 1);
        rs1 += __shfl_xor_sync(0xffffffffu, rs1, 2);
        rs2 += __shfl_xor_sync(0xffffffffu, rs2, 1);
        rs2 += __shfl_xor_sync(0xffffffffu, rs2, 2);
        l1 = l1 * al1 + rs1;
        l2 = l2 * al2 + rs2;
#pragma unroll
        for (int nt = 0; nt < 8; nt++) {
            o[nt][0] *= al1; o[nt][1] *= al1;
            o[nt][2] *= al2; o[nt][3] *= al2;
        }

        // ---- store P (warp-private rows) tf32-rounded
        {
            const int rr1 = Rm + (lane >> 2);
            const int rr2 = rr1 + 8;
#pragma unroll
            for (int nt = 0; nt < 8; nt++) {
                const int c = nt * 8 + 2 * (lane & 3);
                uint32_t a1 = Ps + rr1 * 256 + (((uint32_t)((c >> 2) ^ (rr1 & 7))) << 4) + (c & 3) * 4;
                sts_v2(a1, f2tf(sfr[nt][0]), f2tf(sfr[nt][1]));
                uint32_t a2 = Ps + rr2 * 256 + (((uint32_t)((c >> 2) ^ (rr2 & 7))) << 4) + (c & 3) * 4;
                sts_v2(a2, f2tf(sfr[nt][2]), f2tf(sfr[nt][3]));
            }
        }
        __syncwarp();

        // ---- O += P V
#pragma unroll
        for (int sp = 0; sp < 4; sp++) {
            uint32_t a0[4], a1[4];
            {
                int row = Rm + (lane & 7) + ((lane >> 3) & 1) * 8;
                uint32_t uu0 = (uint32_t)(2 * (2 * sp) + (lane >> 4));
                ldsm4(Ps + row * 256 + ((uu0 ^ (uint32_t)(row & 7)) << 4), a0);
                uint32_t uu1 = (uint32_t)(2 * (2 * sp + 1) + (lane >> 4));
                ldsm4(Ps + row * 256 + ((uu1 ^ (uint32_t)(row & 7)) << 4), a1);
            }
#pragma unroll
            for (int nt = 0; nt < 8; nt++) {
                uint32_t bq[4];
                int row = nt * 8 + (lane & 7);
                uint32_t uu = (uint32_t)(sp * 4 + (lane >> 3));
                ldsm4(VtB[b] + row * 256 + ((uu ^ (uint32_t)(row & 7)) << 4), bq);
                mma8(o[nt], a0, &bq[0]);
                mma8(o[nt], a1, &bq[2]);
            }
        }
    }

    // ---- epilogue: normalize, tf32-round, write g_Ctx [N,S,D]
    const float inv1 = 1.f / l1, inv2 = 1.f / l2;
    const int r1g = qt * QT + Rm + (lane >> 2);
    float* C1 = g_Ctx + ((size_t)n * Seq + r1g) * Dd + h * HDim;
    float* C2 = C1 + (size_t)8 * Dd;
#pragma unroll
    for (int nt = 0; nt < 8; nt++) {
        const int c = nt * 8 + 2 * (lane & 3);
        float2 v1, v2;
        v1.x = f2tf(o[nt][0] * inv1); v1.y = f2tf(o[nt][1] * inv1);
        v2.x = f2tf(o[nt][2] * inv2); v2.y = f2tf(o[nt][3] * inv2);
        *(float2*)&C1[c] = v1;
        *(float2*)&C2[c] = v2;
    }
}

// ===========================================================================
extern "C" void kernel_launch(void* const* d_in, const int* in_sizes, int n_in,
                              void* d_out, int out_size)
{
    (void)in_sizes; (void)n_in; (void)out_size;
    const float* X  = (const float*)d_in[0];
    const float* Wq = (const float*)d_in[1];
    const float* bq = (const float*)d_in[2];
    const float* Wk = (const float*)d_in[3];
    const float* bk = (const float*)d_in[4];
    const float* Wv = (const float*)d_in[5];
    const float* bv = (const float*)d_in[6];
    const float* Wo = (const float*)d_in[7];
    const float* bo = (const float*)d_in[8];

    const int gemm_smem  = GNST * GSTAGE;         // 96KB
    const int flash_smem = 4 * 16384 + 32768;     // 96KB
    cudaFuncSetAttribute(qkv_tc_kernel,
                         cudaFuncAttributeMaxDynamicSharedMemorySize, gemm_smem);
    cudaFuncSetAttribute(oproj_tc_kernel,
                         cudaFuncAttributeMaxDynamicSharedMemorySize, gemm_smem);
    cudaFuncSetAttribute(flash_tc_kernel,
                         cudaFuncAttributeMaxDynamicSharedMemorySize, flash_smem);

    round_kernel<<<(2 * (1 << 20)) / 256, 256>>>(X, Wq, Wk, Wv, Wo);

    dim3 gqkv(Dd / 128, (NBatch * Seq) / 128, 3);
    qkv_tc_kernel<<<gqkv, 256, gemm_smem>>>(bq, bk, bv);

    flash_tc_kernel<<<dim3(Seq / QT, Hh, NBatch), 256, flash_smem>>>();

    dim3 go(Dd / 128, (NBatch * Seq) / 128);
    oproj_tc_kernel<<<go, 256, gemm_smem>>>(bo, (float*)d_out);
}

// round 7
// speedup vs baseline: 4.4783x; 1.0017x over previous
#include <cuda_runtime.h>
#include <cstdint>

#define Dd     1024
#define Hh     16
#define HDim   64
#define NBatch 2
#define Seq    2048

// Scratch
__device__ float g_Q  [NBatch * Hh * Seq * HDim];   // [N,H,S,hd], tf32, pre-scaled 0.125
__device__ float g_K  [NBatch * Hh * Seq * HDim];   // [N,H,S,hd], tf32
__device__ float g_Vt [NBatch * Hh * HDim * Seq];   // [N,H,hd,S], tf32 (transposed)
__device__ float g_Ctx[NBatch * Seq * Dd];          // [N,S,D], tf32
__device__ float g_Xr [NBatch * Seq * Dd];          // tf32-rounded X
__device__ float g_Wr [4 * Dd * Dd];                // tf32-rounded Wq,Wk,Wv,Wo

// ===========================================================================
// PTX helpers
// ===========================================================================
__device__ __forceinline__ uint32_t cvta_smem(const void* p) {
    uint32_t a;
    asm("{ .reg .u64 t; cvta.to.shared.u64 t, %1; cvt.u32.u64 %0, t; }"
        : "=r"(a) : "l"(p));
    return a;
}
__device__ __forceinline__ float f2tf(float f) {
    uint32_t u;
    asm("cvt.rna.tf32.f32 %0, %1;" : "=r"(u) : "f"(f));
    return __uint_as_float(u);
}
__device__ __forceinline__ void ldsm4(uint32_t addr, uint32_t* d) {
    asm volatile("ldmatrix.sync.aligned.m8n8.x4.shared.b16 {%0,%1,%2,%3}, [%4];"
                 : "=r"(d[0]), "=r"(d[1]), "=r"(d[2]), "=r"(d[3]) : "r"(addr));
}
__device__ __forceinline__ void mma8(float* c, const uint32_t* a, const uint32_t* b) {
    asm volatile(
        "mma.sync.aligned.m16n8k8.row.col.f32.tf32.tf32.f32 "
        "{%0,%1,%2,%3}, {%4,%5,%6,%7}, {%8,%9}, {%0,%1,%2,%3};"
        : "+f"(c[0]), "+f"(c[1]), "+f"(c[2]), "+f"(c[3])
        : "r"(a[0]), "r"(a[1]), "r"(a[2]), "r"(a[3]), "r"(b[0]), "r"(b[1]));
}
__device__ __forceinline__ void cp16(uint32_t dst, const void* src) {
    asm volatile("cp.async.cg.shared.global [%0], [%1], 16;" :: "r"(dst), "l"(src));
}
#define CP_COMMIT() asm volatile("cp.async.commit_group;" ::: "memory")
#define CP_WAIT0()  asm volatile("cp.async.wait_group 0;" ::: "memory")
#define CP_WAIT1()  asm volatile("cp.async.wait_group 1;" ::: "memory")
__device__ __forceinline__ void sts_v4(uint32_t addr, float x, float y, float z, float w) {
    asm volatile("st.shared.v4.f32 [%0], {%1,%2,%3,%4};"
                 :: "r"(addr), "f"(x), "f"(y), "f"(z), "f"(w) : "memory");
}
__device__ __forceinline__ void sts_v2(uint32_t addr, float x, float y) {
    asm volatile("st.shared.v2.f32 [%0], {%1,%2};"
                 :: "r"(addr), "f"(x), "f"(y) : "memory");
}

// ===========================================================================
// Pre-round: tf32-round X and the 4 weight matrices into scratch (once).
// ===========================================================================
__global__ __launch_bounds__(256) void round_kernel(
    const float* __restrict__ X,
    const float* __restrict__ Wq, const float* __restrict__ Wk,
    const float* __restrict__ Wv, const float* __restrict__ Wo)
{
    const uint32_t u = blockIdx.x * blockDim.x + threadIdx.x;   // float4 unit
    const float4* src;
    float4* dst;
    if (u < (1u << 20)) {
        src = (const float4*)X + u;
        dst = (float4*)g_Xr + u;
    } else {
        uint32_t w = u - (1u << 20);
        uint32_t sel = w >> 18;
        uint32_t off = w & ((1u << 18) - 1);
        const float* Ws = (sel == 0) ? Wq : (sel == 1) ? Wk : (sel == 2) ? Wv : Wo;
        src = (const float4*)Ws + off;
        dst = (float4*)g_Wr + w;
    }
    float4 v = *src;
    v.x = f2tf(v.x); v.y = f2tf(v.y); v.z = f2tf(v.z); v.w = f2tf(v.w);
    *dst = v;
}

// ===========================================================================
// tf32 mma.sync GEMM, cp.async 3-stage pipeline (verified at ~135 TMAC active).
// ===========================================================================
#define GSTAGE 32768
#define GNST   3

__device__ __forceinline__ void gemm_issue_stage(
    const float* __restrict__ A, const float* __restrict__ W,
    int m0, int n0, uint32_t sb, int s, int tid)
{
    const uint32_t buf = sb + (uint32_t)(s % GNST) * GSTAGE;
    const int k0 = s * 32;
#pragma unroll
    for (int i = 0; i < 4; i++) {
        const int flat = i * 256 + tid;
        const int r = flat >> 3, u = flat & 7;
        const uint32_t sw = (uint32_t)(u ^ (r & 7)) << 4;
        cp16(buf + r * 128 + sw,         A + (size_t)(m0 + r) * Dd + k0 + u * 4);
        cp16(buf + 16384 + r * 128 + sw, W + (size_t)(n0 + r) * Dd + k0 + u * 4);
    }
}

__device__ __forceinline__ void tc_gemm128(
    const float* __restrict__ A, const float* __restrict__ W,
    int m0, int n0, char* smem, float c[4][4][4])
{
    const int tid = threadIdx.x;
    const int wid = tid >> 5, lane = tid & 31;
    const int wm = wid & 1, wn = wid >> 1;
    const uint32_t sb = cvta_smem(smem);

#pragma unroll
    for (int mt = 0; mt < 4; mt++)
#pragma unroll
        for (int nt = 0; nt < 4; nt++)
#pragma unroll
            for (int k = 0; k < 4; k++) c[mt][nt][k] = 0.f;

    gemm_issue_stage(A, W, m0, n0, sb, 0, tid); CP_COMMIT();
    gemm_issue_stage(A, W, m0, n0, sb, 1, tid); CP_COMMIT();

    for (int k = 0; k < 32; k++) {
        CP_WAIT1();
        __syncthreads();
        if (k + 2 < 32) gemm_issue_stage(A, W, m0, n0, sb, k + 2, tid);
        CP_COMMIT();

        const uint32_t cur = sb + (uint32_t)(k % GNST) * GSTAGE;
        const uint32_t Ab = cur, Bb = cur + 16384;
#pragma unroll
        for (int sp = 0; sp < 2; sp++) {
            uint32_t bq[4][4];
#pragma unroll
            for (int nt = 0; nt < 4; nt++) {
                int row = wn * 32 + nt * 8 + (lane & 7);
                uint32_t uu = (uint32_t)(sp * 4 + (lane >> 3));
                ldsm4(Bb + row * 128 + ((uu ^ (uint32_t)(row & 7)) << 4), bq[nt]);
            }
#pragma unroll
            for (int sh = 0; sh < 2; sh++) {
                const int s = sp * 2 + sh;
                uint32_t aq[4][4];
#pragma unroll
                for (int mt = 0; mt < 4; mt++) {
                    int row = wm * 64 + mt * 16 + (lane & 7) + ((lane >> 3) & 1) * 8;
                    uint32_t uu = (uint32_t)(2 * s + (lane >> 4));
                    ldsm4(Ab + row * 128 + ((uu ^ (uint32_t)(row & 7)) << 4), aq[mt]);
                }
#pragma unroll
                for (int mt = 0; mt < 4; mt++)
#pragma unroll
                    for (int nt = 0; nt < 4; nt++)
                        mma8(c[mt][nt], aq[mt], &bq[nt][sh * 2]);
            }
        }
    }
}

// ===========================================================================
// QKV projection: z = 0/1/2 -> Q/K/V.
// ===========================================================================
__global__ __launch_bounds__(256, 2)
void qkv_tc_kernel(const float* __restrict__ bq, const float* __restrict__ bk,
                   const float* __restrict__ bv)
{
    extern __shared__ char sm[];
    const int z = blockIdx.z;
    const float* W    = g_Wr + (size_t)z * Dd * Dd;
    const float* bias = (z == 0) ? bq : (z == 1) ? bk : bv;

    const int m0 = blockIdx.y * 128;
    const int n0 = blockIdx.x * 128;

    float c[4][4][4];
    tc_gemm128(g_Xr, W, m0, n0, sm, c);

    const int tid = threadIdx.x;
    const int wid = tid >> 5, lane = tid & 31;
    const int wm = wid & 1, wn = wid >> 1;
    const float scl = (z == 0) ? 0.125f : 1.0f;

    if (z < 2) {
        float* dst = (z == 0) ? g_Q : g_K;
#pragma unroll
        for (int mt = 0; mt < 4; mt++) {
#pragma unroll
            for (int h2 = 0; h2 < 2; h2++) {
                const int m = m0 + wm * 64 + mt * 16 + (lane >> 2) + h2 * 8;
                const int b = m >> 11;
                const int s = m & (Seq - 1);
#pragma unroll
                for (int nt = 0; nt < 4; nt++) {
                    const int col = n0 + wn * 32 + nt * 8 + 2 * (lane & 3);
                    const int hh = col >> 6, hd = col & 63;
                    float2 v;
                    v.x = f2tf((c[mt][nt][h2 * 2 + 0] + bias[col]) * scl);
                    v.y = f2tf((c[mt][nt][h2 * 2 + 1] + bias[col + 1]) * scl);
                    *(float2*)&dst[((size_t)(b * Hh + hh) * Seq + s) * HDim + hd] = v;
                }
            }
        }
    } else {
#pragma unroll
        for (int mt = 0; mt < 4; mt++) {
#pragma unroll
            for (int h2 = 0; h2 < 2; h2++) {
                const int m = m0 + wm * 64 + mt * 16 + (lane >> 2) + h2 * 8;
                const int b = m >> 11;
                const int s = m & (Seq - 1);
#pragma unroll
                for (int nt = 0; nt < 4; nt++) {
                    const int col = n0 + wn * 32 + nt * 8 + 2 * (lane & 3);
                    const int hh = col >> 6, hd = col & 63;
                    float* dp = g_Vt + ((size_t)(b * Hh + hh) * HDim + hd) * Seq + s;
                    dp[0]   = f2tf(c[mt][nt][h2 * 2 + 0] + bias[col]);
                    dp[Seq] = f2tf(c[mt][nt][h2 * 2 + 1] + bias[col + 1]);
                }
            }
        }
    }
}

// ===========================================================================
// Output projection
// ===========================================================================
__global__ __launch_bounds__(256, 2)
void oproj_tc_kernel(const float* __restrict__ bo, float* __restrict__ out)
{
    extern __shared__ char sm[];
    const int m0 = blockIdx.y * 128;
    const int n0 = blockIdx.x * 128;

    float c[4][4][4];
    tc_gemm128(g_Ctx, g_Wr + (size_t)3 * Dd * Dd, m0, n0, sm, c);

    const int tid = threadIdx.x;
    const int wid = tid >> 5, lane = tid & 31;
    const int wm = wid & 1, wn = wid >> 1;

#pragma unroll
    for (int mt = 0; mt < 4; mt++) {
#pragma unroll
        for (int h2 = 0; h2 < 2; h2++) {
            const int m = m0 + wm * 64 + mt * 16 + (lane >> 2) + h2 * 8;
#pragma unroll
            for (int nt = 0; nt < 4; nt++) {
                const int col = n0 + wn * 32 + nt * 8 + 2 * (lane & 3);
                float2 v;
                v.x = c[mt][nt][h2 * 2 + 0] + bo[col];
                v.y = c[mt][nt][h2 * 2 + 1] + bo[col + 1];
                *(float2*)&out[(size_t)m * Dd + col] = v;
            }
        }
    }
}

// ===========================================================================
// Flash attention, tf32 mma.sync. 2 CTAs/SM (reg-clamped) so one CTA's
// softmax (MUFU) overlaps the other's HMMA. LPT: big-qt blocks first.
// ===========================================================================
#define QT 128

__global__ __launch_bounds__(256, 2) void flash_tc_kernel()
{
    extern __shared__ char sm[];
    const uint32_t sb = cvta_smem(sm);
    const uint32_t KsB[2] = { sb, sb + 32768 };
    const uint32_t VtB[2] = { sb + 16384, sb + 49152 };
    const uint32_t Ps = sb + 65536;

    const int tid = threadIdx.x, wid = tid >> 5, lane = tid & 31;
    const int qt = (int)gridDim.x - 1 - (int)blockIdx.x;    // LPT: large qt first
    const int h = blockIdx.y, n = blockIdx.z;
    const size_t hoff = (size_t)(n * Hh + h) * Seq * HDim;
    const float* Qg  = g_Q + hoff + (size_t)qt * QT * HDim;
    const float* Kg  = g_K + hoff;
    const float* Vtg = g_Vt + (size_t)(n * Hh + h) * HDim * Seq;

    // ---- Stage Q (128x64) into Ps (rows 256B, swizzled), load fragments
#pragma unroll
    for (int i = 0; i < 8; i++) {
        int flat = i * 256 + tid;
        int r = flat >> 4, uu = flat & 15;
        float4 v = *(const float4*)(Qg + r * 64 + uu * 4);
        sts_v4(Ps + r * 256 + (((uint32_t)(uu ^ (r & 7))) << 4), v.x, v.y, v.z, v.w);
    }
    __syncthreads();
    const int Rm = wid * 16;
    uint32_t qf[8][4];
#pragma unroll
    for (int s = 0; s < 8; s++) {
        int row = Rm + (lane & 7) + ((lane >> 3) & 1) * 8;
        uint32_t uu = (uint32_t)(2 * s + (lane >> 4));
        ldsm4(Ps + row * 256 + ((uu ^ (uint32_t)(row & 7)) << 4), qf[s]);
    }
    __syncthreads();

    float o[8][4];
#pragma unroll
    for (int nt = 0; nt < 8; nt++)
#pragma unroll
        for (int k = 0; k < 4; k++) o[nt][k] = 0.f;
    float m1 = -1e30f, m2 = -1e30f, l1 = 0.f, l2 = 0.f;

    const int nkt = 2 * qt + 2;

    {
#pragma unroll
        for (int i = 0; i < 4; i++) {
            int flat = i * 256 + tid;
            int r = flat >> 4, uu = flat & 15;
            uint32_t sw = ((uint32_t)(uu ^ (r & 7))) << 4;
            cp16(KsB[0] + r * 256 + sw, Kg + r * 64 + uu * 4);
            cp16(VtB[0] + r * 256 + sw, Vtg + (size_t)r * Seq + uu * 4);
        }
        CP_COMMIT();
    }

    for (int j = 0; j < nkt; j++) {
        CP_WAIT0();
        __syncthreads();
        const int b = j & 1;
        if (j + 1 < nkt) {
            const float* kg = Kg + (size_t)(j + 1) * 64 * HDim;
            const int tb = (j + 1) * 64;
            const int nb = b ^ 1;
#pragma unroll
            for (int i = 0; i < 4; i++) {
                int flat = i * 256 + tid;
                int r = flat >> 4, uu = flat & 15;
                uint32_t sw = ((uint32_t)(uu ^ (r & 7))) << 4;
                cp16(KsB[nb] + r * 256 + sw, kg + r * 64 + uu * 4);
                cp16(VtB[nb] + r * 256 + sw, Vtg + (size_t)r * Seq + tb + uu * 4);
            }
            CP_COMMIT();
        }

        // ---- S = Q K^T (Q pre-scaled)
        float sfr[8][4];
#pragma unroll
        for (int nt = 0; nt < 8; nt++)
#pragma unroll
            for (int k = 0; k < 4; k++) sfr[nt][k] = 0.f;
#pragma unroll
        for (int sp = 0; sp < 4; sp++) {
#pragma unroll
            for (int nt = 0; nt < 8; nt++) {
                uint32_t bq[4];
                int row = nt * 8 + (lane & 7);
                uint32_t uu = (uint32_t)(sp * 4 + (lane >> 3));
                ldsm4(KsB[b] + row * 256 + ((uu ^ (uint32_t)(row & 7)) << 4), bq);
                mma8(sfr[nt], qf[2 * sp], &bq[0]);
                mma8(sfr[nt], qf[2 * sp + 1], &bq[2]);
            }
        }

        // ---- causal mask (last two kt tiles only)
        const int r1 = qt * QT + Rm + (lane >> 2);
        if (j >= 2 * qt) {
            const int cb = j * 64 + 2 * (lane & 3);
#pragma unroll
            for (int nt = 0; nt < 8; nt++) {
                const int c0 = cb + nt * 8;
                if (c0     > r1)     sfr[nt][0] = -1e30f;
                if (c0 + 1 > r1)     sfr[nt][1] = -1e30f;
                if (c0     > r1 + 8) sfr[nt][2] = -1e30f;
                if (c0 + 1 > r1 + 8) sfr[nt][3] = -1e30f;
            }
        }

        // ---- online softmax
        float mt1 = -1e30f, mt2 = -1e30f;
#pragma unroll
        for (int nt = 0; nt < 8; nt++) {
            mt1 = fmaxf(mt1, fmaxf(sfr[nt][0], sfr[nt][1]));
            mt2 = fmaxf(mt2, fmaxf(sfr[nt][2], sfr[nt][3]));
        }
        mt1 = fmaxf(mt1, __shfl_xor_sync(0xffffffffu, mt1, 1));
        mt1 = fmaxf(mt1, __shfl_xor_sync(0xffffffffu, mt1, 2));
        mt2 = fmaxf(mt2, __shfl_xor_sync(0xffffffffu, mt2, 1));
        mt2 = fmaxf(mt2, __shfl_xor_sync(0xffffffffu, mt2, 2));

        const float mn1 = fmaxf(m1, mt1), al1 = __expf(m1 - mn1);
        const float mn2 = fmaxf(m2, mt2), al2 = __expf(m2 - mn2);
        m1 = mn1; m2 = mn2;
        float rs1 = 0.f, rs2 = 0.f;
#pragma unroll
        for (int nt = 0; nt < 8; nt++) {
            sfr[nt][0] = __expf(sfr[nt][0] - m1); rs1 += sfr[nt][0];
            sfr[nt][1] = __expf(sfr[nt][1] - m1); rs1 += sfr[nt][1];
            sfr[nt][2] = __expf(sfr[nt][2] - m2); rs2 += sfr[nt][2];
            sfr[nt][3] = __expf(sfr[nt][3] - m2); rs2 += sfr[nt][3];
        }
        rs1 += __shfl_xor_sync(0xffffffffu, rs1, 1);
        rs1 += __shfl_xor_sync(0xffffffffu, rs1, 2);
        rs2 += __shfl_xor_sync(0xffffffffu, rs2, 1);
        rs2 += __shfl_xor_sync(0xffffffffu, rs2, 2);
        l1 = l1 * al1 + rs1;
        l2 = l2 * al2 + rs2;
#pragma unroll
        for (int nt = 0; nt < 8; nt++) {
            o[nt][0] *= al1; o[nt][1] *= al1;
            o[nt][2] *= al2; o[nt][3] *= al2;
        }

        // ---- store P (warp-private rows) tf32-rounded
        {
            const int rr1 = Rm + (lane >> 2);
            const int rr2 = rr1 + 8;
#pragma unroll
            for (int nt = 0; nt < 8; nt++) {
                const int c = nt * 8 + 2 * (lane & 3);
                uint32_t a1 = Ps + rr1 * 256 + (((uint32_t)((c >> 2) ^ (rr1 & 7))) << 4) + (c & 3) * 4;
                sts_v2(a1, f2tf(sfr[nt][0]), f2tf(sfr[nt][1]));
                uint32_t a2 = Ps + rr2 * 256 + (((uint32_t)((c >> 2) ^ (rr2 & 7))) << 4) + (c & 3) * 4;
                sts_v2(a2, f2tf(sfr[nt][2]), f2tf(sfr[nt][3]));
            }
        }
        __syncwarp();

        // ---- O += P V
#pragma unroll
        for (int sp = 0; sp < 4; sp++) {
            uint32_t a0[4], a1[4];
            {
                int row = Rm + (lane & 7) + ((lane >> 3) & 1) * 8;
                uint32_t uu0 = (uint32_t)(2 * (2 * sp) + (lane >> 4));
                ldsm4(Ps + row * 256 + ((uu0 ^ (uint32_t)(row & 7)) << 4), a0);
                uint32_t uu1 = (uint32_t)(2 * (2 * sp + 1) + (lane >> 4));
                ldsm4(Ps + row * 256 + ((uu1 ^ (uint32_t)(row & 7)) << 4), a1);
            }
#pragma unroll
            for (int nt = 0; nt < 8; nt++) {
                uint32_t bq[4];
                int row = nt * 8 + (lane & 7);
                uint32_t uu = (uint32_t)(sp * 4 + (lane >> 3));
                ldsm4(VtB[b] + row * 256 + ((uu ^ (uint32_t)(row & 7)) << 4), bq);
                mma8(o[nt], a0, &bq[0]);
                mma8(o[nt], a1, &bq[2]);
            }
        }
    }

    // ---- epilogue: normalize, tf32-round, write g_Ctx [N,S,D]
    const float inv1 = 1.f / l1, inv2 = 1.f / l2;
    const int r1g = qt * QT + Rm + (lane >> 2);
    float* C1 = g_Ctx + ((size_t)n * Seq + r1g) * Dd + h * HDim;
    float* C2 = C1 + (size_t)8 * Dd;
#pragma unroll
    for (int nt = 0; nt < 8; nt++) {
        const int c = nt * 8 + 2 * (lane & 3);
        float2 v1, v2;
        v1.x = f2tf(o[nt][0] * inv1); v1.y = f2tf(o[nt][1] * inv1);
        v2.x = f2tf(o[nt][2] * inv2); v2.y = f2tf(o[nt][3] * inv2);
        *(float2*)&C1[c] = v1;
        *(float2*)&C2[c] = v2;
    }
}

// ===========================================================================
extern "C" void kernel_launch(void* const* d_in, const int* in_sizes, int n_in,
                              void* d_out, int out_size)
{
    (void)in_sizes; (void)n_in; (void)out_size;
    const float* X  = (const float*)d_in[0];
    const float* Wq = (const float*)d_in[1];
    const float* bq = (const float*)d_in[2];
    const float* Wk = (const float*)d_in[3];
    const float* bk = (const float*)d_in[4];
    const float* Wv = (const float*)d_in[5];
    const float* bv = (const float*)d_in[6];
    const float* Wo = (const float*)d_in[7];
    const float* bo = (const float*)d_in[8];

    const int gemm_smem  = GNST * GSTAGE;         // 96KB
    const int flash_smem = 4 * 16384 + 32768;     // 96KB
    cudaFuncSetAttribute(qkv_tc_kernel,
                         cudaFuncAttributeMaxDynamicSharedMemorySize, gemm_smem);
    cudaFuncSetAttribute(oproj_tc_kernel,
                         cudaFuncAttributeMaxDynamicSharedMemorySize, gemm_smem);
    cudaFuncSetAttribute(flash_tc_kernel,
                         cudaFuncAttributeMaxDynamicSharedMemorySize, flash_smem);

    round_kernel<<<(2 * (1 << 20)) / 256, 256>>>(X, Wq, Wk, Wv, Wo);

    dim3 gqkv(Dd / 128, (NBatch * Seq) / 128, 3);
    qkv_tc_kernel<<<gqkv, 256, gemm_smem>>>(bq, bk, bv);

    flash_tc_kernel<<<dim3(Seq / QT, Hh, NBatch), 256, flash_smem>>>();

    dim3 go(Dd / 128, (NBatch * Seq) / 128);
    oproj_tc_kernel<<<go, 256, gemm_smem>>>(bo, (float*)d_out);
}